// round 4
// baseline (speedup 1.0000x reference)
#include <cuda_runtime.h>
#include <cstdint>

#define NN 50000
#define NE 200000
#define HH 512
#define G3 1536

// ---------------- device scratch (static, no allocation) ----------------
__device__ int g_is64;
__device__ int g_src[NE];
__device__ int g_dst[NE];
__device__ int g_inp[NN];
__device__ int g_rowptr[NN + 1];
__device__ int g_cursor[NN];
__device__ int g_csr[NE];
__device__ float g_x0[(size_t)NN * HH];
__device__ float g_x1[(size_t)NN * HH];
__device__ float g_S[(size_t)NN * HH];
__device__ float g_Wp[2][(size_t)HH * G3];

// ---------------- helpers ----------------
__device__ __forceinline__ uint32_t f2tf(float f) {
    uint32_t u;
    asm("cvt.rna.tf32.f32 %0, %1;" : "=r"(u) : "f"(f));
    return u;
}

__device__ __forceinline__ void mma8(float* c, uint32_t a0, uint32_t a1,
                                     uint32_t a2, uint32_t a3,
                                     uint32_t b0, uint32_t b1) {
    asm volatile(
        "mma.sync.aligned.m16n8k8.row.col.f32.tf32.tf32.f32 "
        "{%0,%1,%2,%3},{%4,%5,%6,%7},{%8,%9},{%0,%1,%2,%3};"
        : "+f"(c[0]), "+f"(c[1]), "+f"(c[2]), "+f"(c[3])
        : "r"(a0), "r"(a1), "r"(a2), "r"(a3), "r"(b0), "r"(b1));
}

__device__ __forceinline__ float sigm(float v) { return 1.f / (1.f + __expf(-v)); }
__device__ __forceinline__ float tanh_fast(float v) { return 1.f - 2.f / (__expf(2.f * v) + 1.f); }

// ---------------- dtype detection: int64 vs int32 indices ----------------
__global__ void k_detect(const int* __restrict__ A) {
    __shared__ int nz;
    if (threadIdx.x == 0) nz = 0;
    __syncthreads();
    // If data is int64 (values in [0,50000)), every high word is 0.
    if (A[2 * threadIdx.x + 1] != 0) atomicOr(&nz, 1);
    __syncthreads();
    if (threadIdx.x == 0) g_is64 = (nz == 0) ? 1 : 0;
}

// convert edges + inputs to int32 scratch; zero rowptr
__global__ void k_prep(const void* __restrict__ Ab, const void* __restrict__ Ib) {
    int idx = blockIdx.x * blockDim.x + threadIdx.x;
    int is64 = g_is64;
    if (idx < 2 * NE) {
        long long v = is64 ? ((const long long*)Ab)[idx]
                           : (long long)((const int*)Ab)[idx];
        if (idx < NE) g_src[idx] = (int)v;
        else          g_dst[idx - NE] = (int)v;
    } else if (idx < 2 * NE + NN) {
        int i = idx - 2 * NE;
        long long v = is64 ? ((const long long*)Ib)[i]
                           : (long long)((const int*)Ib)[i];
        g_inp[i] = (int)v;
    } else if (idx < 2 * NE + NN + NN + 1) {
        g_rowptr[idx - 2 * NE - NN] = 0;
    }
}

// x0 = emb[inputs]
__global__ void k_gx0(const float* __restrict__ emb) {
    int i = blockIdx.x * blockDim.x + threadIdx.x;  // over NN*128 float4
    if (i < NN * (HH / 4)) {
        int row = i >> 7, c = i & 127;
        ((float4*)g_x0)[i] =
            ((const float4*)(emb + (size_t)g_inp[row] * HH))[c];
    }
}

// ---------------- CSR build ----------------
__global__ void k_hist() {
    int e = blockIdx.x * blockDim.x + threadIdx.x;
    if (e < NE) atomicAdd(&g_rowptr[g_dst[e] + 1], 1);
}

__global__ void k_scan() {
    __shared__ int sh[1024];
    int t = threadIdx.x;
    int carry = 0;
    for (int base = 0; base < NN; base += 1024) {
        int i = base + t;
        int v = (i < NN) ? g_rowptr[i + 1] : 0;
        sh[t] = v;
        __syncthreads();
        for (int off = 1; off < 1024; off <<= 1) {
            int u = (t >= off) ? sh[t - off] : 0;
            __syncthreads();
            sh[t] += u;
            __syncthreads();
        }
        if (i < NN) g_rowptr[i + 1] = carry + sh[t];
        carry += sh[1023];
        __syncthreads();
    }
}

__global__ void k_cur() {
    int i = blockIdx.x * blockDim.x + threadIdx.x;
    if (i < NN) g_cursor[i] = g_rowptr[i];
}

__global__ void k_fill() {
    int e = blockIdx.x * blockDim.x + threadIdx.x;
    if (e < NE) {
        int p = atomicAdd(&g_cursor[g_dst[e]], 1);
        g_csr[p] = g_src[e];
    }
}

// S[node] = sum over in-edges of x[src]   (one block per node, 128 thr = 512 floats)
__global__ void k_gsum(int xsel) {
    const float* __restrict__ X = xsel ? g_x1 : g_x0;
    int node = blockIdx.x;
    int beg = g_rowptr[node], end = g_rowptr[node + 1];
    float4 acc = make_float4(0.f, 0.f, 0.f, 0.f);
    for (int j = beg; j < end; j++) {
        int s = g_csr[j];
        float4 v = *(const float4*)(X + (size_t)s * HH + threadIdx.x * 4);
        acc.x += v.x; acc.y += v.y; acc.z += v.z; acc.w += v.w;
    }
    *(float4*)(g_S + (size_t)node * HH + threadIdx.x * 4) = acc;
}

// ---------------- Wp[l] = W_l @ w_ih^T   [512,1536], tf32 mma ----------------
__global__ void __launch_bounds__(256) k_wp(const float* __restrict__ W,
                                            const float* __restrict__ Wih,
                                            int layer) {
    float* __restrict__ C = g_Wp[layer];
    __shared__ __align__(16) uint32_t As[64][36];
    __shared__ __align__(16) uint32_t Bs[32][36];  // [col][k]
    const int tid = threadIdx.x;
    const int lane = tid & 31, wid = tid >> 5;
    const int wm = wid & 3, wn = wid >> 2;
    const int g8 = lane >> 2, t4 = lane & 3;
    const int i0 = blockIdx.y * 64;   // k-rows of Wp
    const int c0 = blockIdx.x * 32;   // j-cols of Wp
    float acc[8];
#pragma unroll
    for (int b = 0; b < 8; b++) acc[b] = 0.f;

    for (int kt = 0; kt < 16; kt++) {
        const int kk0 = kt * 32;
        __syncthreads();
#pragma unroll
        for (int r2 = 0; r2 < 2; r2++) {  // A: 64x32 = 512 f4
            int v = tid + 256 * r2;
            int row = v >> 3, c4 = v & 7;
            float4 a = *(const float4*)(W + (size_t)(i0 + row) * HH + kk0 + c4 * 4);
            uint4 u; u.x = f2tf(a.x); u.y = f2tf(a.y); u.z = f2tf(a.z); u.w = f2tf(a.w);
            *(uint4*)&As[row][c4 * 4] = u;
        }
        {  // B: 32x32 = 256 f4
            int col = tid >> 3, k4 = tid & 7;
            float4 b = *(const float4*)(Wih + (size_t)(c0 + col) * HH + kk0 + k4 * 4);
            uint4 u; u.x = f2tf(b.x); u.y = f2tf(b.y); u.z = f2tf(b.z); u.w = f2tf(b.w);
            *(uint4*)&Bs[col][k4 * 4] = u;
        }
        __syncthreads();
#pragma unroll
        for (int ks = 0; ks < 4; ks++) {
            const int kb = ks * 8;
            uint32_t a0 = As[wm * 16 + g8][kb + t4];
            uint32_t a1 = As[wm * 16 + g8 + 8][kb + t4];
            uint32_t a2 = As[wm * 16 + g8][kb + t4 + 4];
            uint32_t a3 = As[wm * 16 + g8 + 8][kb + t4 + 4];
#pragma unroll
            for (int nt = 0; nt < 2; nt++) {
                int nc = wn * 16 + nt * 8 + g8;
                uint32_t b0 = Bs[nc][kb + t4];
                uint32_t b1 = Bs[nc][kb + t4 + 4];
                mma8(acc + nt * 4, a0, a1, a2, a3, b0, b1);
            }
        }
    }
#pragma unroll
    for (int nt = 0; nt < 2; nt++)
#pragma unroll
        for (int j = 0; j < 4; j++) {
            int row = i0 + wm * 16 + g8 + ((j >> 1) << 3);
            int col = c0 + wn * 16 + nt * 8 + t4 * 2 + (j & 1);
            C[(size_t)row * G3 + col] = acc[nt * 4 + j];
        }
}

// ---------------- fused GEMM + GRU ----------------
// gi_{r,z,n} = S @ Wp ; gh_{r,z,n} = X @ w_hh^T ; epilogue -> out
__global__ void __launch_bounds__(512) k_fused(int layer, int xsel, int final_out,
                                               float* __restrict__ dout,
                                               const float* __restrict__ Whh,
                                               const float* __restrict__ bih,
                                               const float* __restrict__ bhh) {
    const float* __restrict__ X = xsel ? g_x1 : g_x0;
    const float* __restrict__ Wp = g_Wp[layer];
    float* __restrict__ out = final_out ? dout : g_x1;

    __shared__ __align__(16) uint32_t As[128][36];
    __shared__ __align__(16) uint32_t Bs[3][32][36];  // p0: [g][k][col], p1: [g][col][k]

    const int tid = threadIdx.x;
    const int lane = tid & 31, wid = tid >> 5;
    const int wm = wid & 7, wn = wid >> 3;
    const int g8 = lane >> 2, t4 = lane & 3;
    const int i0 = blockIdx.y * 128;
    const int c0 = blockIdx.x * 32;

    float acc[6][8];
#pragma unroll
    for (int a = 0; a < 6; a++)
#pragma unroll
        for (int b = 0; b < 8; b++) acc[a][b] = 0.f;

#pragma unroll
    for (int p = 0; p < 2; p++) {
        const float* __restrict__ Ap = p ? X : g_S;
        for (int kt = 0; kt < 16; kt++) {
            const int kk0 = kt * 32;
            __syncthreads();
            // A tile: 128x32 = 1024 f4
#pragma unroll
            for (int r2 = 0; r2 < 2; r2++) {
                int v = tid + 512 * r2;
                int row = v >> 3, c4 = v & 7;
                int gi = i0 + row;
                float4 a = make_float4(0.f, 0.f, 0.f, 0.f);
                if (gi < NN) a = *(const float4*)(Ap + (size_t)gi * HH + kk0 + c4 * 4);
                uint4 u; u.x = f2tf(a.x); u.y = f2tf(a.y); u.z = f2tf(a.z); u.w = f2tf(a.w);
                *(uint4*)&As[row][c4 * 4] = u;
            }
            // B tiles: 3 gates x 32 x 32 = 768 f4
            for (int v = tid; v < 768; v += 512) {
                int g = v >> 8, w = v & 255;
                if (p == 0) {
                    int k = w >> 3, c4 = w & 7;
                    float4 b = *(const float4*)(Wp + (size_t)(kk0 + k) * G3 + g * HH + c0 + c4 * 4);
                    uint4 u; u.x = f2tf(b.x); u.y = f2tf(b.y); u.z = f2tf(b.z); u.w = f2tf(b.w);
                    *(uint4*)&Bs[g][k][c4 * 4] = u;
                } else {
                    int col = w >> 3, k4 = w & 7;
                    float4 b = *(const float4*)(Whh + (size_t)(g * HH + c0 + col) * HH + kk0 + k4 * 4);
                    uint4 u; u.x = f2tf(b.x); u.y = f2tf(b.y); u.z = f2tf(b.z); u.w = f2tf(b.w);
                    *(uint4*)&Bs[g][col][k4 * 4] = u;
                }
            }
            __syncthreads();
#pragma unroll
            for (int ks = 0; ks < 4; ks++) {
                const int kb = ks * 8;
                uint32_t a0 = As[wm * 16 + g8][kb + t4];
                uint32_t a1 = As[wm * 16 + g8 + 8][kb + t4];
                uint32_t a2 = As[wm * 16 + g8][kb + t4 + 4];
                uint32_t a3 = As[wm * 16 + g8 + 8][kb + t4 + 4];
#pragma unroll
                for (int g = 0; g < 3; g++) {
#pragma unroll
                    for (int nt = 0; nt < 2; nt++) {
                        int nc = wn * 16 + nt * 8 + g8;
                        uint32_t b0, b1;
                        if (p == 0) {
                            b0 = Bs[g][kb + t4][nc];
                            b1 = Bs[g][kb + t4 + 4][nc];
                        } else {
                            b0 = Bs[g][nc][kb + t4];
                            b1 = Bs[g][nc][kb + t4 + 4];
                        }
                        mma8(acc[3 * p + g] + nt * 4, a0, a1, a2, a3, b0, b1);
                    }
                }
            }
        }
    }

    // epilogue: GRU gates
#pragma unroll
    for (int nt = 0; nt < 2; nt++)
#pragma unroll
        for (int j = 0; j < 4; j++) {
            int row = i0 + wm * 16 + g8 + ((j >> 1) << 3);
            int col = c0 + wn * 16 + nt * 8 + t4 * 2 + (j & 1);
            if (row < NN) {
                int q = nt * 4 + j;
                float vr = acc[0][q] + __ldg(&bih[col])          + acc[3][q] + __ldg(&bhh[col]);
                float vz = acc[1][q] + __ldg(&bih[col + HH])     + acc[4][q] + __ldg(&bhh[col + HH]);
                float r = sigm(vr);
                float z = sigm(vz);
                float in_ = acc[2][q] + __ldg(&bih[col + 2 * HH]);
                float hn  = acc[5][q] + __ldg(&bhh[col + 2 * HH]);
                float n = tanh_fast(in_ + r * hn);
                float h = X[(size_t)row * HH + col];
                out[(size_t)row * HH + col] = (1.f - z) * n + z * h;
            }
        }
}

// ---------------- launch ----------------
extern "C" void kernel_launch(void* const* d_in, const int* in_sizes, int n_in,
                              void* d_out, int out_size) {
    const void* inputs = d_in[0];
    const void* A      = d_in[1];
    const float* emb    = (const float*)d_in[2];
    const float* weight = (const float*)d_in[3];
    const float* w_ih   = (const float*)d_in[4];
    const float* w_hh   = (const float*)d_in[5];
    const float* b_ih   = (const float*)d_in[6];
    const float* b_hh   = (const float*)d_in[7];
    float* out = (float*)d_out;

    k_detect<<<1, 128>>>((const int*)A);
    int T = 2 * NE + NN + NN + 1;
    k_prep<<<(T + 255) / 256, 256>>>(A, inputs);
    k_gx0<<<(NN * (HH / 4) + 255) / 256, 256>>>(emb);
    k_hist<<<(NE + 255) / 256, 256>>>();
    k_scan<<<1, 1024>>>();
    k_cur<<<(NN + 255) / 256, 256>>>();
    k_fill<<<(NE + 255) / 256, 256>>>();
    for (int l = 0; l < 2; l++)
        k_wp<<<dim3(G3 / 32, HH / 64), 256>>>(weight + (size_t)l * HH * HH, w_ih, l);
    for (int l = 0; l < 2; l++) {
        k_gsum<<<NN, 128>>>(l);
        k_fused<<<dim3(HH / 32, (NN + 127) / 128), 512>>>(
            l, l, (l == 1) ? 1 : 0, out, w_hh, b_ih, b_hh);
    }
}

// round 5
// speedup vs baseline: 2.0300x; 2.0300x over previous
#include <cuda_runtime.h>
#include <cstdint>

#define NN 50000
#define NE 200000
#define HH 512
#define G3 1536

// ---------------- device scratch (static, no allocation) ----------------
__device__ int g_is64;
__device__ int g_src[NE];
__device__ int g_dst[NE];
__device__ int g_inp[NN];
__device__ int g_rowptr[NN + 1];
__device__ int g_cursor[NN];
__device__ int g_csr[NE];
__device__ float g_x0[(size_t)NN * HH];
__device__ float g_x1[(size_t)NN * HH];
__device__ float g_S[(size_t)NN * HH];
// Bmat[l] = [ Wp_l (512 rows) ; w_hh^T (512 rows) ], 1024 x 1536, tf32-rounded
__device__ float g_Bmat[2][1024][G3];

// ---------------- helpers ----------------
__device__ __forceinline__ uint32_t f2tf(float f) {
    uint32_t u;
    asm("cvt.rna.tf32.f32 %0, %1;" : "=r"(u) : "f"(f));
    return u;
}

__device__ __forceinline__ void mma8(float* c, uint32_t a0, uint32_t a1,
                                     uint32_t a2, uint32_t a3,
                                     uint32_t b0, uint32_t b1) {
    asm volatile(
        "mma.sync.aligned.m16n8k8.row.col.f32.tf32.tf32.f32 "
        "{%0,%1,%2,%3},{%4,%5,%6,%7},{%8,%9},{%0,%1,%2,%3};"
        : "+f"(c[0]), "+f"(c[1]), "+f"(c[2]), "+f"(c[3])
        : "r"(a0), "r"(a1), "r"(a2), "r"(a3), "r"(b0), "r"(b1));
}

__device__ __forceinline__ float sigm(float v) { return 1.f / (1.f + __expf(-v)); }
__device__ __forceinline__ float tanh_fast(float v) { return 1.f - 2.f / (__expf(2.f * v) + 1.f); }

__device__ __forceinline__ void cpasync16(uint32_t d, const void* s) {
    asm volatile("cp.async.cg.shared.global [%0], [%1], 16;" :: "r"(d), "l"(s));
}
__device__ __forceinline__ void cp_commit() { asm volatile("cp.async.commit_group;"); }
__device__ __forceinline__ void cp_wait1() { asm volatile("cp.async.wait_group 1;" ::: "memory"); }
__device__ __forceinline__ void cp_wait0() { asm volatile("cp.async.wait_group 0;" ::: "memory"); }

// ---------------- dtype detection: int64 vs int32 indices ----------------
__global__ void k_detect(const int* __restrict__ A) {
    __shared__ int nz;
    if (threadIdx.x == 0) nz = 0;
    __syncthreads();
    if (A[2 * threadIdx.x + 1] != 0) atomicOr(&nz, 1);
    __syncthreads();
    if (threadIdx.x == 0) g_is64 = (nz == 0) ? 1 : 0;
}

__global__ void k_prep(const void* __restrict__ Ab, const void* __restrict__ Ib) {
    int idx = blockIdx.x * blockDim.x + threadIdx.x;
    int is64 = g_is64;
    if (idx < 2 * NE) {
        long long v = is64 ? ((const long long*)Ab)[idx]
                           : (long long)((const int*)Ab)[idx];
        if (idx < NE) g_src[idx] = (int)v;
        else          g_dst[idx - NE] = (int)v;
    } else if (idx < 2 * NE + NN) {
        int i = idx - 2 * NE;
        long long v = is64 ? ((const long long*)Ib)[i]
                           : (long long)((const int*)Ib)[i];
        g_inp[i] = (int)v;
    } else if (idx < 2 * NE + NN + NN + 1) {
        g_rowptr[idx - 2 * NE - NN] = 0;
    }
}

__global__ void k_gx0(const float* __restrict__ emb) {
    int i = blockIdx.x * blockDim.x + threadIdx.x;
    if (i < NN * (HH / 4)) {
        int row = i >> 7, c = i & 127;
        ((float4*)g_x0)[i] =
            ((const float4*)(emb + (size_t)g_inp[row] * HH))[c];
    }
}

// ---------------- CSR build ----------------
__global__ void k_hist() {
    int e = blockIdx.x * blockDim.x + threadIdx.x;
    if (e < NE) atomicAdd(&g_rowptr[g_dst[e] + 1], 1);
}

__global__ void k_scan() {
    __shared__ int sh[1024];
    int t = threadIdx.x;
    int carry = 0;
    for (int base = 0; base < NN; base += 1024) {
        int i = base + t;
        int v = (i < NN) ? g_rowptr[i + 1] : 0;
        sh[t] = v;
        __syncthreads();
        for (int off = 1; off < 1024; off <<= 1) {
            int u = (t >= off) ? sh[t - off] : 0;
            __syncthreads();
            sh[t] += u;
            __syncthreads();
        }
        if (i < NN) g_rowptr[i + 1] = carry + sh[t];
        carry += sh[1023];
        __syncthreads();
    }
}

__global__ void k_cur() {
    int i = blockIdx.x * blockDim.x + threadIdx.x;
    if (i < NN) g_cursor[i] = g_rowptr[i];
}

__global__ void k_fill() {
    int e = blockIdx.x * blockDim.x + threadIdx.x;
    if (e < NE) {
        int p = atomicAdd(&g_cursor[g_dst[e]], 1);
        g_csr[p] = g_src[e];
    }
}

// S[node] = sum over in-edges of x[src], tf32-rounded (GEMM-only consumer)
__global__ void k_gsum(int xsel) {
    const float* __restrict__ X = xsel ? g_x1 : g_x0;
    int node = blockIdx.x;
    int beg = g_rowptr[node], end = g_rowptr[node + 1];
    float4 acc = make_float4(0.f, 0.f, 0.f, 0.f);
    for (int j = beg; j < end; j++) {
        int s = g_csr[j];
        float4 v = *(const float4*)(X + (size_t)s * HH + threadIdx.x * 4);
        acc.x += v.x; acc.y += v.y; acc.z += v.z; acc.w += v.w;
    }
    float4 o;
    o.x = __uint_as_float(f2tf(acc.x));
    o.y = __uint_as_float(f2tf(acc.y));
    o.z = __uint_as_float(f2tf(acc.z));
    o.w = __uint_as_float(f2tf(acc.w));
    *(float4*)(g_S + (size_t)node * HH + threadIdx.x * 4) = o;
}

// ---------------- Bmat rows [0:512) : Wp[l] = W_l @ w_ih^T ----------------
__global__ void __launch_bounds__(256) k_wp(const float* __restrict__ W,
                                            const float* __restrict__ Wih,
                                            int layer) {
    float* __restrict__ C = &g_Bmat[layer][0][0];
    __shared__ __align__(16) uint32_t As[64][36];
    __shared__ __align__(16) uint32_t Bs[32][36];
    const int tid = threadIdx.x;
    const int lane = tid & 31, wid = tid >> 5;
    const int wm = wid & 3, wn = wid >> 2;
    const int g8 = lane >> 2, t4 = lane & 3;
    const int i0 = blockIdx.y * 64;
    const int c0 = blockIdx.x * 32;
    float acc[8];
#pragma unroll
    for (int b = 0; b < 8; b++) acc[b] = 0.f;

    for (int kt = 0; kt < 16; kt++) {
        const int kk0 = kt * 32;
        __syncthreads();
#pragma unroll
        for (int r2 = 0; r2 < 2; r2++) {
            int v = tid + 256 * r2;
            int row = v >> 3, c4 = v & 7;
            float4 a = *(const float4*)(W + (size_t)(i0 + row) * HH + kk0 + c4 * 4);
            uint4 u; u.x = f2tf(a.x); u.y = f2tf(a.y); u.z = f2tf(a.z); u.w = f2tf(a.w);
            *(uint4*)&As[row][c4 * 4] = u;
        }
        {
            int col = tid >> 3, k4 = tid & 7;
            float4 b = *(const float4*)(Wih + (size_t)(c0 + col) * HH + kk0 + k4 * 4);
            uint4 u; u.x = f2tf(b.x); u.y = f2tf(b.y); u.z = f2tf(b.z); u.w = f2tf(b.w);
            *(uint4*)&Bs[col][k4 * 4] = u;
        }
        __syncthreads();
#pragma unroll
        for (int ks = 0; ks < 4; ks++) {
            const int kb = ks * 8;
            uint32_t a0 = As[wm * 16 + g8][kb + t4];
            uint32_t a1 = As[wm * 16 + g8 + 8][kb + t4];
            uint32_t a2 = As[wm * 16 + g8][kb + t4 + 4];
            uint32_t a3 = As[wm * 16 + g8 + 8][kb + t4 + 4];
#pragma unroll
            for (int nt = 0; nt < 2; nt++) {
                int nc = wn * 16 + nt * 8 + g8;
                uint32_t b0 = Bs[nc][kb + t4];
                uint32_t b1 = Bs[nc][kb + t4 + 4];
                mma8(acc + nt * 4, a0, a1, a2, a3, b0, b1);
            }
        }
    }
#pragma unroll
    for (int nt = 0; nt < 2; nt++)
#pragma unroll
        for (int j = 0; j < 4; j++) {
            int row = i0 + wm * 16 + g8 + ((j >> 1) << 3);
            int col = c0 + wn * 16 + nt * 8 + t4 * 2 + (j & 1);
            C[(size_t)row * G3 + col] = __uint_as_float(f2tf(acc[nt * 4 + j]));
        }
}

// ---------------- Bmat rows [512:1024) : w_hh^T (shared by both layers) ----
__global__ void k_whhT(const float* __restrict__ whh) {
    __shared__ float t[32][33];
    int tx = threadIdx.x, ty = threadIdx.y;
    int k0 = blockIdx.x * 32, j0 = blockIdx.y * 32;
    t[ty][tx] = whh[(size_t)(j0 + ty) * HH + k0 + tx];
    __syncthreads();
    float v = __uint_as_float(f2tf(t[tx][ty]));  // = whh[j0+tx][k0+ty]
    g_Bmat[0][512 + k0 + ty][j0 + tx] = v;
    g_Bmat[1][512 + k0 + ty][j0 + tx] = v;
}

// ---------------- fused GEMM + GRU, merged K=1024, double-buffered ---------
// A = [S | X] (K 0..511 = S, 512..1023 = X); B = Bmat[l]
// accR/accZ accumulate full K; accN1 = S@Wp_n (K<512), accN2 = X@Whh_n^T
#define SMEM_WORDS (2 * 128 * 36 + 2 * 3 * 32 * 72)

__global__ void __launch_bounds__(512, 1) k_fused(int layer, int xsel, int final_out,
                                                  float* __restrict__ dout,
                                                  const float* __restrict__ bih,
                                                  const float* __restrict__ bhh) {
    extern __shared__ uint32_t sm[];
    uint32_t(*As)[128][36] = (uint32_t(*)[128][36])sm;
    uint32_t(*Bs)[3][32][72] = (uint32_t(*)[3][32][72])(sm + 2 * 128 * 36);

    const float* __restrict__ X = xsel ? g_x1 : g_x0;
    const float* __restrict__ Bm = &g_Bmat[layer][0][0];
    float* __restrict__ out = final_out ? dout : g_x1;

    const int tid = threadIdx.x;
    const int lane = tid & 31, wid = tid >> 5;
    const int wm = wid & 3, wn = wid >> 2;
    const int g8 = lane >> 2, t4 = lane & 3;
    const int i0 = blockIdx.y * 128;
    const int c0 = blockIdx.x * 64;

    const uint32_t sbase = (uint32_t)__cvta_generic_to_shared(sm);
    const uint32_t sA = sbase;
    const uint32_t sB = sbase + 2 * 128 * 36 * 4;

    float accR[2][2][4], accZ[2][2][4], accN1[2][2][4], accN2[2][2][4];
#pragma unroll
    for (int mf = 0; mf < 2; mf++)
#pragma unroll
        for (int nf = 0; nf < 2; nf++)
#pragma unroll
            for (int j = 0; j < 4; j++) {
                accR[mf][nf][j] = 0.f; accZ[mf][nf][j] = 0.f;
                accN1[mf][nf][j] = 0.f; accN2[mf][nf][j] = 0.f;
            }

    // ---- async tile loader ----
    auto load_tile = [&](int buf, int kt) {
        const float* Ap = (kt < 16) ? g_S : X;
        const int koff = (kt & 15) * 32;
#pragma unroll
        for (int r2 = 0; r2 < 2; r2++) {
            int v = tid + 512 * r2;
            int row = v >> 3, c4 = v & 7;
            int gr = i0 + row;
            if (gr >= NN) gr = NN - 1;   // duplicated rows discarded in epilogue
            const float* src = Ap + (size_t)gr * HH + koff + c4 * 4;
            uint32_t d = sA + (((buf * 128 + row) * 36 + c4 * 4) << 2);
            cpasync16(d, src);
        }
#pragma unroll
        for (int r3 = 0; r3 < 3; r3++) {
            int v = tid + 512 * r3;
            int g = v >> 9, w = v & 511;
            int k = w >> 4, c4 = w & 15;
            const float* src = Bm + (size_t)(kt * 32 + k) * G3 + g * HH + c0 + c4 * 4;
            uint32_t d = sB + ((((buf * 3 + g) * 32 + k) * 72 + c4 * 4) << 2);
            cpasync16(d, src);
        }
    };

    int buf = 0;
    load_tile(0, 0);
    cp_commit();

    for (int kt = 0; kt < 32; kt++) {
        if (kt < 31) {
            load_tile(buf ^ 1, kt + 1);
            cp_commit();
            cp_wait1();
        } else {
            cp_wait0();
        }
        __syncthreads();
        const bool xo = (kt >= 16);
#pragma unroll
        for (int ks = 0; ks < 4; ks++) {
            const int kb = ks * 8;
            uint32_t a[2][4];
#pragma unroll
            for (int mf = 0; mf < 2; mf++) {
                int r0 = wm * 32 + mf * 16 + g8;
                a[mf][0] = As[buf][r0][kb + t4];
                a[mf][1] = As[buf][r0 + 8][kb + t4];
                a[mf][2] = As[buf][r0][kb + t4 + 4];
                a[mf][3] = As[buf][r0 + 8][kb + t4 + 4];
            }
            if (xo) {  // X half is not pre-rounded
#pragma unroll
                for (int mf = 0; mf < 2; mf++)
#pragma unroll
                    for (int q = 0; q < 4; q++)
                        a[mf][q] = f2tf(__uint_as_float(a[mf][q]));
            }
#pragma unroll
            for (int g = 0; g < 3; g++) {
#pragma unroll
                for (int nf = 0; nf < 2; nf++) {
                    int nc = wn * 16 + nf * 8 + g8;
                    uint32_t b0 = Bs[buf][g][kb + t4][nc];
                    uint32_t b1 = Bs[buf][g][kb + t4 + 4][nc];
#pragma unroll
                    for (int mf = 0; mf < 2; mf++) {
                        if (g == 0)
                            mma8(accR[mf][nf], a[mf][0], a[mf][1], a[mf][2], a[mf][3], b0, b1);
                        else if (g == 1)
                            mma8(accZ[mf][nf], a[mf][0], a[mf][1], a[mf][2], a[mf][3], b0, b1);
                        else if (!xo)
                            mma8(accN1[mf][nf], a[mf][0], a[mf][1], a[mf][2], a[mf][3], b0, b1);
                        else
                            mma8(accN2[mf][nf], a[mf][0], a[mf][1], a[mf][2], a[mf][3], b0, b1);
                    }
                }
            }
        }
        __syncthreads();
        buf ^= 1;
    }

    // ---- GRU epilogue ----
#pragma unroll
    for (int mf = 0; mf < 2; mf++)
#pragma unroll
        for (int nf = 0; nf < 2; nf++)
#pragma unroll
            for (int j = 0; j < 4; j++) {
                int row = i0 + wm * 32 + mf * 16 + g8 + ((j >> 1) << 3);
                int col = c0 + wn * 16 + nf * 8 + t4 * 2 + (j & 1);
                if (row < NN) {
                    float vr = accR[mf][nf][j] + __ldg(bih + col) + __ldg(bhh + col);
                    float vz = accZ[mf][nf][j] + __ldg(bih + col + HH) + __ldg(bhh + col + HH);
                    float r = sigm(vr);
                    float z = sigm(vz);
                    float n = tanh_fast(accN1[mf][nf][j] + __ldg(bih + col + 2 * HH) +
                                        r * (accN2[mf][nf][j] + __ldg(bhh + col + 2 * HH)));
                    float h = X[(size_t)row * HH + col];
                    out[(size_t)row * HH + col] = (1.f - z) * n + z * h;
                }
            }
}

// ---------------- launch ----------------
extern "C" void kernel_launch(void* const* d_in, const int* in_sizes, int n_in,
                              void* d_out, int out_size) {
    const void* inputs = d_in[0];
    const void* A      = d_in[1];
    const float* emb    = (const float*)d_in[2];
    const float* weight = (const float*)d_in[3];
    const float* w_ih   = (const float*)d_in[4];
    const float* w_hh   = (const float*)d_in[5];
    const float* b_ih   = (const float*)d_in[6];
    const float* b_hh   = (const float*)d_in[7];
    float* out = (float*)d_out;

    cudaFuncSetAttribute(k_fused, cudaFuncAttributeMaxDynamicSharedMemorySize,
                         SMEM_WORDS * 4);

    k_detect<<<1, 128>>>((const int*)A);
    int T = 2 * NE + NN + NN + 1;
    k_prep<<<(T + 255) / 256, 256>>>(A, inputs);
    k_gx0<<<(NN * (HH / 4) + 255) / 256, 256>>>(emb);
    k_hist<<<(NE + 255) / 256, 256>>>();
    k_scan<<<1, 1024>>>();
    k_cur<<<(NN + 255) / 256, 256>>>();
    k_fill<<<(NE + 255) / 256, 256>>>();
    k_whhT<<<dim3(HH / 32, G3 / 32), dim3(32, 32)>>>(w_hh);
    for (int l = 0; l < 2; l++)
        k_wp<<<dim3(G3 / 32, HH / 64), 256>>>(weight + (size_t)l * HH * HH, w_ih, l);
    for (int l = 0; l < 2; l++) {
        k_gsum<<<NN, 128>>>(l);
        k_fused<<<dim3(HH / 64, (NN + 127) / 128), 512, SMEM_WORDS * 4>>>(
            l, l, (l == 1) ? 1 : 0, out, b_ih, b_hh);
    }
}

// round 6
// speedup vs baseline: 2.0306x; 1.0003x over previous
#include <cuda_runtime.h>
#include <cstdint>

#define NN 50000
#define NE 200000
#define HH 512
#define G3 1536

// ---------------- device scratch (static, no allocation) ----------------
__device__ int g_is64;
__device__ int g_src[NE];
__device__ int g_dst[NE];
__device__ int g_inp[NN];
__device__ int g_rowptr[NN + 1];
__device__ int g_cursor[NN];
__device__ int g_csr[NE];
__device__ float g_x0[(size_t)NN * HH];
__device__ float g_x1[(size_t)NN * HH];
__device__ float g_S[(size_t)NN * HH];
// Bmat[l] = [ Wp_l (512 rows) ; w_hh^T (512 rows) ], 1024 x 1536, tf32-rounded
__device__ float g_Bmat[2][1024][G3];

// ---------------- helpers ----------------
__device__ __forceinline__ uint32_t f2tf(float f) {
    uint32_t u;
    asm("cvt.rna.tf32.f32 %0, %1;" : "=r"(u) : "f"(f));
    return u;
}

__device__ __forceinline__ void mma8(float* c, uint32_t a0, uint32_t a1,
                                     uint32_t a2, uint32_t a3,
                                     uint32_t b0, uint32_t b1) {
    asm volatile(
        "mma.sync.aligned.m16n8k8.row.col.f32.tf32.tf32.f32 "
        "{%0,%1,%2,%3},{%4,%5,%6,%7},{%8,%9},{%0,%1,%2,%3};"
        : "+f"(c[0]), "+f"(c[1]), "+f"(c[2]), "+f"(c[3])
        : "r"(a0), "r"(a1), "r"(a2), "r"(a3), "r"(b0), "r"(b1));
}

__device__ __forceinline__ float sigm(float v) { return 1.f / (1.f + __expf(-v)); }
__device__ __forceinline__ float tanh_fast(float v) { return 1.f - 2.f / (__expf(2.f * v) + 1.f); }

__device__ __forceinline__ void cpasync16(uint32_t d, const void* s) {
    asm volatile("cp.async.cg.shared.global [%0], [%1], 16;" :: "r"(d), "l"(s));
}
__device__ __forceinline__ void cp_commit() { asm volatile("cp.async.commit_group;"); }
__device__ __forceinline__ void cp_wait1() { asm volatile("cp.async.wait_group 1;" ::: "memory"); }
__device__ __forceinline__ void cp_wait0() { asm volatile("cp.async.wait_group 0;" ::: "memory"); }

// ---------------- dtype detection: int64 vs int32 indices ----------------
__global__ void k_detect(const int* __restrict__ A) {
    __shared__ int nz;
    if (threadIdx.x == 0) nz = 0;
    __syncthreads();
    if (A[2 * threadIdx.x + 1] != 0) atomicOr(&nz, 1);
    __syncthreads();
    if (threadIdx.x == 0) g_is64 = (nz == 0) ? 1 : 0;
}

__global__ void k_prep(const void* __restrict__ Ab, const void* __restrict__ Ib) {
    int idx = blockIdx.x * blockDim.x + threadIdx.x;
    int is64 = g_is64;
    if (idx < 2 * NE) {
        long long v = is64 ? ((const long long*)Ab)[idx]
                           : (long long)((const int*)Ab)[idx];
        if (idx < NE) g_src[idx] = (int)v;
        else          g_dst[idx - NE] = (int)v;
    } else if (idx < 2 * NE + NN) {
        int i = idx - 2 * NE;
        long long v = is64 ? ((const long long*)Ib)[i]
                           : (long long)((const int*)Ib)[i];
        g_inp[i] = (int)v;
    } else if (idx < 2 * NE + NN + NN + 1) {
        g_rowptr[idx - 2 * NE - NN] = 0;
    }
}

__global__ void k_gx0(const float* __restrict__ emb) {
    int i = blockIdx.x * blockDim.x + threadIdx.x;
    if (i < NN * (HH / 4)) {
        int row = i >> 7, c = i & 127;
        ((float4*)g_x0)[i] =
            ((const float4*)(emb + (size_t)g_inp[row] * HH))[c];
    }
}

// ---------------- CSR build ----------------
__global__ void k_hist() {
    int e = blockIdx.x * blockDim.x + threadIdx.x;
    if (e < NE) atomicAdd(&g_rowptr[g_dst[e] + 1], 1);
}

__global__ void k_scan() {
    __shared__ int sh[1024];
    int t = threadIdx.x;
    int carry = 0;
    for (int base = 0; base < NN; base += 1024) {
        int i = base + t;
        int v = (i < NN) ? g_rowptr[i + 1] : 0;
        sh[t] = v;
        __syncthreads();
        for (int off = 1; off < 1024; off <<= 1) {
            int u = (t >= off) ? sh[t - off] : 0;
            __syncthreads();
            sh[t] += u;
            __syncthreads();
        }
        if (i < NN) g_rowptr[i + 1] = carry + sh[t];
        carry += sh[1023];
        __syncthreads();
    }
}

__global__ void k_cur() {
    int i = blockIdx.x * blockDim.x + threadIdx.x;
    if (i < NN) g_cursor[i] = g_rowptr[i];
}

__global__ void k_fill() {
    int e = blockIdx.x * blockDim.x + threadIdx.x;
    if (e < NE) {
        int p = atomicAdd(&g_cursor[g_dst[e]], 1);
        g_csr[p] = g_src[e];
    }
}

// S[node] = sum over in-edges of x[src], tf32-rounded (GEMM-only consumer)
__global__ void k_gsum(int xsel) {
    const float* __restrict__ X = xsel ? g_x1 : g_x0;
    int node = blockIdx.x;
    int beg = g_rowptr[node], end = g_rowptr[node + 1];
    float4 acc = make_float4(0.f, 0.f, 0.f, 0.f);
    for (int j = beg; j < end; j++) {
        int s = g_csr[j];
        float4 v = *(const float4*)(X + (size_t)s * HH + threadIdx.x * 4);
        acc.x += v.x; acc.y += v.y; acc.z += v.z; acc.w += v.w;
    }
    float4 o;
    o.x = __uint_as_float(f2tf(acc.x));
    o.y = __uint_as_float(f2tf(acc.y));
    o.z = __uint_as_float(f2tf(acc.z));
    o.w = __uint_as_float(f2tf(acc.w));
    *(float4*)(g_S + (size_t)node * HH + threadIdx.x * 4) = o;
}

// ---------------- Bmat rows [0:512) : Wp[l] = W_l @ w_ih^T ----------------
__global__ void __launch_bounds__(256) k_wp(const float* __restrict__ W,
                                            const float* __restrict__ Wih,
                                            int layer) {
    float* __restrict__ C = &g_Bmat[layer][0][0];
    __shared__ __align__(16) uint32_t As[64][36];
    __shared__ __align__(16) uint32_t Bs[32][36];
    const int tid = threadIdx.x;
    const int lane = tid & 31, wid = tid >> 5;
    const int wm = wid & 3, wn = wid >> 2;
    const int g8 = lane >> 2, t4 = lane & 3;
    const int i0 = blockIdx.y * 64;
    const int c0 = blockIdx.x * 32;
    float acc[8];
#pragma unroll
    for (int b = 0; b < 8; b++) acc[b] = 0.f;

    for (int kt = 0; kt < 16; kt++) {
        const int kk0 = kt * 32;
        __syncthreads();
#pragma unroll
        for (int r2 = 0; r2 < 2; r2++) {
            int v = tid + 256 * r2;
            int row = v >> 3, c4 = v & 7;
            float4 a = *(const float4*)(W + (size_t)(i0 + row) * HH + kk0 + c4 * 4);
            uint4 u; u.x = f2tf(a.x); u.y = f2tf(a.y); u.z = f2tf(a.z); u.w = f2tf(a.w);
            *(uint4*)&As[row][c4 * 4] = u;
        }
        {
            int col = tid >> 3, k4 = tid & 7;
            float4 b = *(const float4*)(Wih + (size_t)(c0 + col) * HH + kk0 + k4 * 4);
            uint4 u; u.x = f2tf(b.x); u.y = f2tf(b.y); u.z = f2tf(b.z); u.w = f2tf(b.w);
            *(uint4*)&Bs[col][k4 * 4] = u;
        }
        __syncthreads();
#pragma unroll
        for (int ks = 0; ks < 4; ks++) {
            const int kb = ks * 8;
            uint32_t a0 = As[wm * 16 + g8][kb + t4];
            uint32_t a1 = As[wm * 16 + g8 + 8][kb + t4];
            uint32_t a2 = As[wm * 16 + g8][kb + t4 + 4];
            uint32_t a3 = As[wm * 16 + g8 + 8][kb + t4 + 4];
#pragma unroll
            for (int nt = 0; nt < 2; nt++) {
                int nc = wn * 16 + nt * 8 + g8;
                uint32_t b0 = Bs[nc][kb + t4];
                uint32_t b1 = Bs[nc][kb + t4 + 4];
                mma8(acc + nt * 4, a0, a1, a2, a3, b0, b1);
            }
        }
    }
#pragma unroll
    for (int nt = 0; nt < 2; nt++)
#pragma unroll
        for (int j = 0; j < 4; j++) {
            int row = i0 + wm * 16 + g8 + ((j >> 1) << 3);
            int col = c0 + wn * 16 + nt * 8 + t4 * 2 + (j & 1);
            C[(size_t)row * G3 + col] = __uint_as_float(f2tf(acc[nt * 4 + j]));
        }
}

// ---------------- Bmat rows [512:1024) : w_hh^T (shared by both layers) ----
__global__ void k_whhT(const float* __restrict__ whh) {
    __shared__ float t[32][33];
    int tx = threadIdx.x, ty = threadIdx.y;
    int k0 = blockIdx.x * 32, j0 = blockIdx.y * 32;
    t[ty][tx] = whh[(size_t)(j0 + ty) * HH + k0 + tx];
    __syncthreads();
    float v = __uint_as_float(f2tf(t[tx][ty]));  // = whh[j0+tx][k0+ty]
    g_Bmat[0][512 + k0 + ty][j0 + tx] = v;
    g_Bmat[1][512 + k0 + ty][j0 + tx] = v;
}

// ---------------- fused GEMM + GRU, merged K=1024, double-buffered ---------
// A = [S | X] (K 0..511 = S, 512..1023 = X); B = Bmat[l]
// accR/accZ accumulate full K; accN1 = S@Wp_n (K<512), accN2 = X@Whh_n^T
#define SMEM_WORDS (2 * 128 * 36 + 2 * 3 * 32 * 72)

__global__ void __launch_bounds__(512, 1) k_fused(int layer, int xsel, int final_out,
                                                  float* __restrict__ dout,
                                                  const float* __restrict__ bih,
                                                  const float* __restrict__ bhh) {
    extern __shared__ uint32_t sm[];
    uint32_t(*As)[128][36] = (uint32_t(*)[128][36])sm;
    uint32_t(*Bs)[3][32][72] = (uint32_t(*)[3][32][72])(sm + 2 * 128 * 36);

    const float* __restrict__ X = xsel ? g_x1 : g_x0;
    const float* __restrict__ Bm = &g_Bmat[layer][0][0];
    float* __restrict__ out = final_out ? dout : g_x1;

    const int tid = threadIdx.x;
    const int lane = tid & 31, wid = tid >> 5;
    const int wm = wid & 3, wn = wid >> 2;
    const int g8 = lane >> 2, t4 = lane & 3;
    const int i0 = blockIdx.y * 128;
    const int c0 = blockIdx.x * 64;

    const uint32_t sbase = (uint32_t)__cvta_generic_to_shared(sm);
    const uint32_t sA = sbase;
    const uint32_t sB = sbase + 2 * 128 * 36 * 4;

    float accR[2][2][4], accZ[2][2][4], accN1[2][2][4], accN2[2][2][4];
#pragma unroll
    for (int mf = 0; mf < 2; mf++)
#pragma unroll
        for (int nf = 0; nf < 2; nf++)
#pragma unroll
            for (int j = 0; j < 4; j++) {
                accR[mf][nf][j] = 0.f; accZ[mf][nf][j] = 0.f;
                accN1[mf][nf][j] = 0.f; accN2[mf][nf][j] = 0.f;
            }

    // ---- async tile loader ----
    auto load_tile = [&](int buf, int kt) {
        const float* Ap = (kt < 16) ? g_S : X;
        const int koff = (kt & 15) * 32;
#pragma unroll
        for (int r2 = 0; r2 < 2; r2++) {
            int v = tid + 512 * r2;
            int row = v >> 3, c4 = v & 7;
            int gr = i0 + row;
            if (gr >= NN) gr = NN - 1;   // duplicated rows discarded in epilogue
            const float* src = Ap + (size_t)gr * HH + koff + c4 * 4;
            uint32_t d = sA + (((buf * 128 + row) * 36 + c4 * 4) << 2);
            cpasync16(d, src);
        }
#pragma unroll
        for (int r3 = 0; r3 < 3; r3++) {
            int v = tid + 512 * r3;
            int g = v >> 9, w = v & 511;
            int k = w >> 4, c4 = w & 15;
            const float* src = Bm + (size_t)(kt * 32 + k) * G3 + g * HH + c0 + c4 * 4;
            uint32_t d = sB + ((((buf * 3 + g) * 32 + k) * 72 + c4 * 4) << 2);
            cpasync16(d, src);
        }
    };

    int buf = 0;
    load_tile(0, 0);
    cp_commit();

    for (int kt = 0; kt < 32; kt++) {
        if (kt < 31) {
            load_tile(buf ^ 1, kt + 1);
            cp_commit();
            cp_wait1();
        } else {
            cp_wait0();
        }
        __syncthreads();
        const bool xo = (kt >= 16);
#pragma unroll
        for (int ks = 0; ks < 4; ks++) {
            const int kb = ks * 8;
            uint32_t a[2][4];
#pragma unroll
            for (int mf = 0; mf < 2; mf++) {
                int r0 = wm * 32 + mf * 16 + g8;
                a[mf][0] = As[buf][r0][kb + t4];
                a[mf][1] = As[buf][r0 + 8][kb + t4];
                a[mf][2] = As[buf][r0][kb + t4 + 4];
                a[mf][3] = As[buf][r0 + 8][kb + t4 + 4];
            }
            if (xo) {  // X half is not pre-rounded
#pragma unroll
                for (int mf = 0; mf < 2; mf++)
#pragma unroll
                    for (int q = 0; q < 4; q++)
                        a[mf][q] = f2tf(__uint_as_float(a[mf][q]));
            }
#pragma unroll
            for (int g = 0; g < 3; g++) {
#pragma unroll
                for (int nf = 0; nf < 2; nf++) {
                    int nc = wn * 16 + nf * 8 + g8;
                    uint32_t b0 = Bs[buf][g][kb + t4][nc];
                    uint32_t b1 = Bs[buf][g][kb + t4 + 4][nc];
#pragma unroll
                    for (int mf = 0; mf < 2; mf++) {
                        if (g == 0)
                            mma8(accR[mf][nf], a[mf][0], a[mf][1], a[mf][2], a[mf][3], b0, b1);
                        else if (g == 1)
                            mma8(accZ[mf][nf], a[mf][0], a[mf][1], a[mf][2], a[mf][3], b0, b1);
                        else if (!xo)
                            mma8(accN1[mf][nf], a[mf][0], a[mf][1], a[mf][2], a[mf][3], b0, b1);
                        else
                            mma8(accN2[mf][nf], a[mf][0], a[mf][1], a[mf][2], a[mf][3], b0, b1);
                    }
                }
            }
        }
        __syncthreads();
        buf ^= 1;
    }

    // ---- GRU epilogue ----
#pragma unroll
    for (int mf = 0; mf < 2; mf++)
#pragma unroll
        for (int nf = 0; nf < 2; nf++)
#pragma unroll
            for (int j = 0; j < 4; j++) {
                int row = i0 + wm * 32 + mf * 16 + g8 + ((j >> 1) << 3);
                int col = c0 + wn * 16 + nf * 8 + t4 * 2 + (j & 1);
                if (row < NN) {
                    float vr = accR[mf][nf][j] + __ldg(bih + col) + __ldg(bhh + col);
                    float vz = accZ[mf][nf][j] + __ldg(bih + col + HH) + __ldg(bhh + col + HH);
                    float r = sigm(vr);
                    float z = sigm(vz);
                    float n = tanh_fast(accN1[mf][nf][j] + __ldg(bih + col + 2 * HH) +
                                        r * (accN2[mf][nf][j] + __ldg(bhh + col + 2 * HH)));
                    float h = X[(size_t)row * HH + col];
                    out[(size_t)row * HH + col] = (1.f - z) * n + z * h;
                }
            }
}

// ---------------- launch ----------------
extern "C" void kernel_launch(void* const* d_in, const int* in_sizes, int n_in,
                              void* d_out, int out_size) {
    const void* inputs = d_in[0];
    const void* A      = d_in[1];
    const float* emb    = (const float*)d_in[2];
    const float* weight = (const float*)d_in[3];
    const float* w_ih   = (const float*)d_in[4];
    const float* w_hh   = (const float*)d_in[5];
    const float* b_ih   = (const float*)d_in[6];
    const float* b_hh   = (const float*)d_in[7];
    float* out = (float*)d_out;

    cudaFuncSetAttribute(k_fused, cudaFuncAttributeMaxDynamicSharedMemorySize,
                         SMEM_WORDS * 4);

    k_detect<<<1, 128>>>((const int*)A);
    int T = 2 * NE + NN + NN + 1;
    k_prep<<<(T + 255) / 256, 256>>>(A, inputs);
    k_gx0<<<(NN * (HH / 4) + 255) / 256, 256>>>(emb);
    k_hist<<<(NE + 255) / 256, 256>>>();
    k_scan<<<1, 1024>>>();
    k_cur<<<(NN + 255) / 256, 256>>>();
    k_fill<<<(NE + 255) / 256, 256>>>();
    k_whhT<<<dim3(HH / 32, G3 / 32), dim3(32, 32)>>>(w_hh);
    for (int l = 0; l < 2; l++)
        k_wp<<<dim3(G3 / 32, HH / 64), 256>>>(weight + (size_t)l * HH * HH, w_ih, l);
    for (int l = 0; l < 2; l++) {
        k_gsum<<<NN, 128>>>(l);
        k_fused<<<dim3(HH / 64, (NN + 127) / 128), 512, SMEM_WORDS * 4>>>(
            l, l, (l == 1) ? 1 : 0, out, b_ih, b_hh);
    }
}

// round 8
// speedup vs baseline: 3.4770x; 1.7123x over previous
#include <cuda_runtime.h>
#include <cuda_fp16.h>
#include <cstdint>

#define NN 50000
#define NE 200000
#define HH 512
#define G3 1536

// ---------------- device scratch (static, no allocation) ----------------
__device__ int g_is64;
__device__ int g_src[NE];
__device__ int g_dst[NE];
__device__ int g_inp[NN];
__device__ int g_rowptr[NN + 1];
__device__ int g_cursor[NN];
__device__ int g_csr[NE];
__device__ __align__(128) float g_x0[(size_t)NN * HH];   // fp32 h-state layer0
__device__ __align__(128) float g_x1[(size_t)NN * HH];   // fp32 h-state layer1
__device__ __align__(128) __half g_x0h[(size_t)NN * HH]; // fp16 GEMM copies
__device__ __align__(128) __half g_x1h[(size_t)NN * HH];
__device__ __align__(128) __half g_Sh[(size_t)NN * HH];
// g_Bh[l][gatecol][k] col-major fp16: cols 0..511 = r, 512..1023 = z, 1024..1535 = n
// k 0..511 = Wp (S pass), 512..1023 = w_hh (X pass)
__device__ __align__(128) __half g_Bh[2][G3][1024];

// ---------------- helpers ----------------
__device__ __forceinline__ uint32_t f2tf(float f) {
    uint32_t u;
    asm("cvt.rna.tf32.f32 %0, %1;" : "=r"(u) : "f"(f));
    return u;
}
__device__ __forceinline__ float sigm(float v) { return 1.f / (1.f + __expf(-v)); }
__device__ __forceinline__ float tanh_fast(float v) { return 1.f - 2.f / (__expf(2.f * v) + 1.f); }

__device__ __forceinline__ void cpasync16(uint32_t d, const void* s) {
    asm volatile("cp.async.cg.shared.global [%0], [%1], 16;" :: "r"(d), "l"(s));
}
__device__ __forceinline__ void cp_commit() { asm volatile("cp.async.commit_group;"); }
__device__ __forceinline__ void cp_wait1() { asm volatile("cp.async.wait_group 1;" ::: "memory"); }
__device__ __forceinline__ void cp_wait0() { asm volatile("cp.async.wait_group 0;" ::: "memory"); }

__device__ __forceinline__ uint32_t smem_u32(const void* p) {
    uint32_t a;
    asm("{ .reg .u64 t; cvta.to.shared.u64 t, %1; cvt.u32.u64 %0, t; }" : "=r"(a) : "l"(p));
    return a;
}

// fp16 mma, fp32 accum
__device__ __forceinline__ void mma16(float* c, uint32_t a0, uint32_t a1,
                                      uint32_t a2, uint32_t a3,
                                      uint32_t b0, uint32_t b1) {
    asm volatile(
        "mma.sync.aligned.m16n8k16.row.col.f32.f16.f16.f32 "
        "{%0,%1,%2,%3},{%4,%5,%6,%7},{%8,%9},{%0,%1,%2,%3};"
        : "+f"(c[0]), "+f"(c[1]), "+f"(c[2]), "+f"(c[3])
        : "r"(a0), "r"(a1), "r"(a2), "r"(a3), "r"(b0), "r"(b1));
}

// ---------------- dtype detection / prep / CSR ----------------
__global__ void k_detect(const int* __restrict__ A) {
    __shared__ int nz;
    if (threadIdx.x == 0) nz = 0;
    __syncthreads();
    if (A[2 * threadIdx.x + 1] != 0) atomicOr(&nz, 1);
    __syncthreads();
    if (threadIdx.x == 0) g_is64 = (nz == 0) ? 1 : 0;
}

__global__ void k_prep(const void* __restrict__ Ab, const void* __restrict__ Ib) {
    int idx = blockIdx.x * blockDim.x + threadIdx.x;
    int is64 = g_is64;
    if (idx < 2 * NE) {
        long long v = is64 ? ((const long long*)Ab)[idx]
                           : (long long)((const int*)Ab)[idx];
        if (idx < NE) g_src[idx] = (int)v;
        else          g_dst[idx - NE] = (int)v;
    } else if (idx < 2 * NE + NN) {
        int i = idx - 2 * NE;
        long long v = is64 ? ((const long long*)Ib)[i]
                           : (long long)((const int*)Ib)[i];
        g_inp[i] = (int)v;
    } else if (idx < 2 * NE + NN + NN + 1) {
        g_rowptr[idx - 2 * NE - NN] = 0;
    }
}

// x0 = emb[inputs] (fp32 + fp16 copies)
__global__ void k_gx0(const float* __restrict__ emb) {
    int i = blockIdx.x * blockDim.x + threadIdx.x;
    if (i < NN * (HH / 4)) {
        int row = i >> 7, c = i & 127;
        float4 v = ((const float4*)(emb + (size_t)g_inp[row] * HH))[c];
        ((float4*)g_x0)[i] = v;
        __half2 h0 = __floats2half2_rn(v.x, v.y);
        __half2 h1 = __floats2half2_rn(v.z, v.w);
        uint2 u = make_uint2(*(uint32_t*)&h0, *(uint32_t*)&h1);
        *(uint2*)(g_x0h + (size_t)row * HH + c * 4) = u;
    }
}

__global__ void k_hist() {
    int e = blockIdx.x * blockDim.x + threadIdx.x;
    if (e < NE) atomicAdd(&g_rowptr[g_dst[e] + 1], 1);
}

__global__ void k_scan() {
    __shared__ int sh[1024];
    int t = threadIdx.x;
    int carry = 0;
    for (int base = 0; base < NN; base += 1024) {
        int i = base + t;
        int v = (i < NN) ? g_rowptr[i + 1] : 0;
        sh[t] = v;
        __syncthreads();
        for (int off = 1; off < 1024; off <<= 1) {
            int u = (t >= off) ? sh[t - off] : 0;
            __syncthreads();
            sh[t] += u;
            __syncthreads();
        }
        if (i < NN) g_rowptr[i + 1] = carry + sh[t];
        carry += sh[1023];
        __syncthreads();
    }
}

__global__ void k_cur() {
    int i = blockIdx.x * blockDim.x + threadIdx.x;
    if (i < NN) g_cursor[i] = g_rowptr[i];
}

__global__ void k_fill() {
    int e = blockIdx.x * blockDim.x + threadIdx.x;
    if (e < NE) {
        int p = atomicAdd(&g_cursor[g_dst[e]], 1);
        g_csr[p] = g_src[e];
    }
}

// S[node] = sum over in-edges of xh[src] (fp16 gather, fp32 accum, fp16 store)
__global__ void k_gsum(int xsel) {
    const __half* __restrict__ X = xsel ? g_x1h : g_x0h;
    int node = blockIdx.x;
    int beg = g_rowptr[node], end = g_rowptr[node + 1];
    float a0 = 0.f, a1 = 0.f, a2 = 0.f, a3 = 0.f;
    for (int j = beg; j < end; j++) {
        int s = g_csr[j];
        uint2 u = *(const uint2*)(X + (size_t)s * HH + threadIdx.x * 4);
        float2 f0 = __half22float2(*(__half2*)&u.x);
        float2 f1 = __half22float2(*(__half2*)&u.y);
        a0 += f0.x; a1 += f0.y; a2 += f1.x; a3 += f1.y;
    }
    __half2 h0 = __floats2half2_rn(a0, a1);
    __half2 h1 = __floats2half2_rn(a2, a3);
    uint2 o = make_uint2(*(uint32_t*)&h0, *(uint32_t*)&h1);
    *(uint2*)(g_Sh + (size_t)node * HH + threadIdx.x * 4) = o;
}

// ---------------- g_Bh k<512 : Wp[l] = W_l @ w_ih^T (tf32 mma, transposed) --
__global__ void __launch_bounds__(256) k_wp(const float* __restrict__ W,
                                            const float* __restrict__ Wih,
                                            int layer) {
    __shared__ __align__(16) uint32_t As[64][36];
    __shared__ __align__(16) uint32_t Bs[32][36];
    const int tid = threadIdx.x;
    const int lane = tid & 31, wid = tid >> 5;
    const int wm = wid & 3, wn = wid >> 2;
    const int g8 = lane >> 2, t4 = lane & 3;
    const int i0 = blockIdx.y * 64;   // k index of Wp
    const int c0 = blockIdx.x * 32;   // gate col
    float acc[8];
#pragma unroll
    for (int b = 0; b < 8; b++) acc[b] = 0.f;

    for (int kt = 0; kt < 16; kt++) {
        const int kk0 = kt * 32;
        __syncthreads();
#pragma unroll
        for (int r2 = 0; r2 < 2; r2++) {
            int v = tid + 256 * r2;
            int row = v >> 3, c4 = v & 7;
            float4 a = *(const float4*)(W + (size_t)(i0 + row) * HH + kk0 + c4 * 4);
            uint4 u; u.x = f2tf(a.x); u.y = f2tf(a.y); u.z = f2tf(a.z); u.w = f2tf(a.w);
            *(uint4*)&As[row][c4 * 4] = u;
        }
        {
            int col = tid >> 3, k4 = tid & 7;
            float4 b = *(const float4*)(Wih + (size_t)(c0 + col) * HH + kk0 + k4 * 4);
            uint4 u; u.x = f2tf(b.x); u.y = f2tf(b.y); u.z = f2tf(b.z); u.w = f2tf(b.w);
            *(uint4*)&Bs[col][k4 * 4] = u;
        }
        __syncthreads();
#pragma unroll
        for (int ks = 0; ks < 4; ks++) {
            const int kb = ks * 8;
            uint32_t a0 = As[wm * 16 + g8][kb + t4];
            uint32_t a1 = As[wm * 16 + g8 + 8][kb + t4];
            uint32_t a2 = As[wm * 16 + g8][kb + t4 + 4];
            uint32_t a3 = As[wm * 16 + g8 + 8][kb + t4 + 4];
#pragma unroll
            for (int nt = 0; nt < 2; nt++) {
                int nc = wn * 16 + nt * 8 + g8;
                uint32_t b0 = Bs[nc][kb + t4];
                uint32_t b1 = Bs[nc][kb + t4 + 4];
                asm volatile(
                    "mma.sync.aligned.m16n8k8.row.col.f32.tf32.tf32.f32 "
                    "{%0,%1,%2,%3},{%4,%5,%6,%7},{%8,%9},{%0,%1,%2,%3};"
                    : "+f"(acc[nt * 4 + 0]), "+f"(acc[nt * 4 + 1]),
                      "+f"(acc[nt * 4 + 2]), "+f"(acc[nt * 4 + 3])
                    : "r"(a0), "r"(a1), "r"(a2), "r"(a3), "r"(b0), "r"(b1));
            }
        }
    }
#pragma unroll
    for (int nt = 0; nt < 2; nt++)
#pragma unroll
        for (int j = 0; j < 4; j++) {
            int krow = i0 + wm * 16 + g8 + ((j >> 1) << 3);
            int col = c0 + wn * 16 + nt * 8 + t4 * 2 + (j & 1);
            g_Bh[layer][col][krow] = __float2half_rn(acc[nt * 4 + j]);
        }
}

// ---------------- g_Bh k in [512:1024) : w_hh (row copy, fp16) -------------
__global__ void k_whh(const float* __restrict__ whh) {
    int i = blockIdx.x * blockDim.x + threadIdx.x;  // over 1536*128 float4
    if (i < G3 * (HH / 4)) {
        int row = i >> 7, c4 = i & 127;
        float4 v = ((const float4*)(whh + (size_t)row * HH))[c4];
        __half2 h0 = __floats2half2_rn(v.x, v.y);
        __half2 h1 = __floats2half2_rn(v.z, v.w);
        uint2 u = make_uint2(*(uint32_t*)&h0, *(uint32_t*)&h1);
        *(uint2*)&g_Bh[0][row][512 + c4 * 4] = u;
        *(uint2*)&g_Bh[1][row][512 + c4 * 4] = u;
    }
}

// ---------------- fused fp16 GEMM + GRU, merged K=1024, double-buffered ----
// Block tile: 128 m x 64 n-cols. 16 warps: wm=wid&3 (m32), wn=wid>>2 (n16).
// k-tile = 64 halves. 16 tiles (8 S-pass + 8 X-pass).
#define STRIDE_H 72                       // halves per smem row (64 + 8 pad)
#define ST_A (128 * STRIDE_H * 2)         // 18432 B
#define ST_B (192 * STRIDE_H * 2)         // 27648 B
#define ST_SZ (ST_A + ST_B)               // 46080 B
#define SM_TOTAL (2 * ST_SZ)              // 92160 B

__global__ void __launch_bounds__(512, 1) k_fused(int layer, int xsel, int final_out,
                                                  float* __restrict__ dout,
                                                  const float* __restrict__ bih,
                                                  const float* __restrict__ bhh) {
    extern __shared__ __align__(16) char smem[];
    const uint32_t sbase = smem_u32(smem);

    const __half* __restrict__ Xh = xsel ? g_x1h : g_x0h;
    const float* __restrict__ Xf = xsel ? g_x1 : g_x0;
    const __half* __restrict__ Bh = &g_Bh[layer][0][0];
    float* __restrict__ out = final_out ? dout : g_x1;

    const int tid = threadIdx.x;
    const int lane = tid & 31, wid = tid >> 5;
    const int wm = wid & 3, wn = wid >> 2;
    const int g8 = lane >> 2, t4 = lane & 3;
    const int i0 = blockIdx.y * 128;
    const int c0 = blockIdx.x * 64;

    float accR[2][2][4], accZ[2][2][4], accN1[2][2][4], accN2[2][2][4];
#pragma unroll
    for (int mf = 0; mf < 2; mf++)
#pragma unroll
        for (int nf = 0; nf < 2; nf++)
#pragma unroll
            for (int j = 0; j < 4; j++) {
                accR[mf][nf][j] = 0.f; accZ[mf][nf][j] = 0.f;
                accN1[mf][nf][j] = 0.f; accN2[mf][nf][j] = 0.f;
            }

    // ---- async tile loader: tile t in 0..15, pass = t>>3, kt = t&7 ----
    auto load_tile = [&](int s, int t) {
        const int pass = t >> 3;
        const int k0 = (t & 7) * 64;   // halves within the 512-half row
        const __half* Ap = pass ? Xh : g_Sh;
        const uint32_t sA = sbase + s * ST_SZ;
        const uint32_t sB = sA + ST_A;
#pragma unroll
        for (int i = 0; i < 2; i++) {   // A: 128 rows x 8 chunks of 16B
            int v = tid + 512 * i;
            int row = v >> 3, c = v & 7;
            int gr = i0 + row;
            if (gr >= NN) gr = NN - 1;  // dup rows discarded in epilogue
            const __half* src = Ap + (size_t)gr * HH + k0 + c * 8;
            cpasync16(sA + (uint32_t)(row * (STRIDE_H * 2) + c * 16), src);
        }
#pragma unroll
        for (int i = 0; i < 3; i++) {   // B: 192 cols x 8 chunks of 16B
            int v = tid + 512 * i;
            int col = v >> 3, c = v & 7;
            int gate = col >> 6, j = col & 63;
            const __half* src = Bh + (size_t)(gate * 512 + c0 + j) * 1024 +
                                pass * 512 + k0 + c * 8;
            cpasync16(sB + (uint32_t)(col * (STRIDE_H * 2) + c * 16), src);
        }
    };

    int buf = 0;
    load_tile(0, 0);
    cp_commit();

    for (int t = 0; t < 16; t++) {
        if (t < 15) {
            load_tile(buf ^ 1, t + 1);
            cp_commit();
            cp_wait1();
        } else {
            cp_wait0();
        }
        __syncthreads();
        const int pass = t >> 3;
        const __half* As = (const __half*)(smem + buf * ST_SZ);
        const __half* Bs = (const __half*)(smem + buf * ST_SZ + ST_A);
#pragma unroll
        for (int ks = 0; ks < 4; ks++) {
            const int kb = ks * 16;
            uint32_t a[2][4];
#pragma unroll
            for (int mf = 0; mf < 2; mf++) {
                const __half* pa = As + (wm * 32 + mf * 16 + g8) * STRIDE_H + kb + 2 * t4;
                a[mf][0] = *(const uint32_t*)(pa);
                a[mf][1] = *(const uint32_t*)(pa + 8 * STRIDE_H);
                a[mf][2] = *(const uint32_t*)(pa + 8);
                a[mf][3] = *(const uint32_t*)(pa + 8 * STRIDE_H + 8);
            }
#pragma unroll
            for (int g = 0; g < 3; g++) {
#pragma unroll
                for (int nf = 0; nf < 2; nf++) {
                    int nc = wn * 16 + nf * 8 + g8;
                    const __half* pb = Bs + (g * 64 + nc) * STRIDE_H + kb + 2 * t4;
                    uint32_t b0 = *(const uint32_t*)(pb);
                    uint32_t b1 = *(const uint32_t*)(pb + 8);
#pragma unroll
                    for (int mf = 0; mf < 2; mf++) {
                        float* dst = (g == 0) ? accR[mf][nf]
                                   : (g == 1) ? accZ[mf][nf]
                                   : (pass == 0) ? accN1[mf][nf] : accN2[mf][nf];
                        mma16(dst, a[mf][0], a[mf][1], a[mf][2], a[mf][3], b0, b1);
                    }
                }
            }
        }
        __syncthreads();
        buf ^= 1;
    }

    // ---- GRU epilogue ----
#pragma unroll
    for (int mf = 0; mf < 2; mf++)
#pragma unroll
        for (int nf = 0; nf < 2; nf++) {
            const int colb = c0 + wn * 16 + nf * 8 + t4 * 2;
#pragma unroll
            for (int half_ = 0; half_ < 2; half_++) {   // j pair: rows g8 / g8+8
                int row = i0 + wm * 32 + mf * 16 + g8 + half_ * 8;
                if (row < NN) {
                    float o[2];
#pragma unroll
                    for (int q = 0; q < 2; q++) {
                        int j = half_ * 2 + q;
                        int cl = colb + q;
                        float vr = accR[mf][nf][j] + __ldg(bih + cl) + __ldg(bhh + cl);
                        float vz = accZ[mf][nf][j] + __ldg(bih + cl + HH) + __ldg(bhh + cl + HH);
                        float r = sigm(vr);
                        float z = sigm(vz);
                        float n = tanh_fast(accN1[mf][nf][j] + __ldg(bih + cl + 2 * HH) +
                                            r * (accN2[mf][nf][j] + __ldg(bhh + cl + 2 * HH)));
                        float h = Xf[(size_t)row * HH + cl];
                        o[q] = (1.f - z) * n + z * h;
                    }
                    *(float2*)(out + (size_t)row * HH + colb) = make_float2(o[0], o[1]);
                    if (!final_out) {
                        __half2 hh = __floats2half2_rn(o[0], o[1]);
                        *(uint32_t*)(g_x1h + (size_t)row * HH + colb) = *(uint32_t*)&hh;
                    }
                }
            }
        }
}

// ---------------- launch ----------------
extern "C" void kernel_launch(void* const* d_in, const int* in_sizes, int n_in,
                              void* d_out, int out_size) {
    const void* inputs = d_in[0];
    const void* A      = d_in[1];
    const float* emb    = (const float*)d_in[2];
    const float* weight = (const float*)d_in[3];
    const float* w_ih   = (const float*)d_in[4];
    const float* w_hh   = (const float*)d_in[5];
    const float* b_ih   = (const float*)d_in[6];
    const float* b_hh   = (const float*)d_in[7];
    float* out = (float*)d_out;

    cudaFuncSetAttribute(k_fused, cudaFuncAttributeMaxDynamicSharedMemorySize, SM_TOTAL);

    k_detect<<<1, 128>>>((const int*)A);
    int T = 2 * NE + NN + NN + 1;
    k_prep<<<(T + 255) / 256, 256>>>(A, inputs);
    k_gx0<<<(NN * (HH / 4) + 255) / 256, 256>>>(emb);
    k_hist<<<(NE + 255) / 256, 256>>>();
    k_scan<<<1, 1024>>>();
    k_cur<<<(NN + 255) / 256, 256>>>();
    k_fill<<<(NE + 255) / 256, 256>>>();
    k_whh<<<(G3 * (HH / 4) + 255) / 256, 256>>>(w_hh);
    for (int l = 0; l < 2; l++)
        k_wp<<<dim3(G3 / 32, HH / 64), 256>>>(weight + (size_t)l * HH * HH, w_ih, l);
    for (int l = 0; l < 2; l++) {
        k_gsum<<<NN, 128>>>(l);
        k_fused<<<dim3(HH / 64, (NN + 127) / 128), 512, SM_TOTAL>>>(
            l, l, (l == 1) ? 1 : 0, out, b_ih, b_hh);
    }
}

// round 10
// speedup vs baseline: 3.6463x; 1.0487x over previous
#include <cuda_runtime.h>
#include <cuda_fp16.h>
#include <cstdint>

#define NN 50000
#define NE 200000
#define HH 512
#define G3 1536

// ---------------- device scratch (static, no allocation) ----------------
__device__ int g_is64;
__device__ int g_src[NE];
__device__ int g_dst[NE];
__device__ int g_inp[NN];
__device__ int g_rowptr[NN + 1];
__device__ int g_cursor[NN];
__device__ int g_csr[NE];
__device__ int g_bsum[64];
__device__ __align__(128) float g_x1[(size_t)NN * HH];   // fp32 h-state after layer0
__device__ __align__(128) __half g_x0h[(size_t)NN * HH]; // fp16 GEMM copies
__device__ __align__(128) __half g_x1h[(size_t)NN * HH];
__device__ __align__(128) __half g_Sh[(size_t)NN * HH];
// g_Bh[l][gatecol][k] col-major fp16: cols 0..511 = r, 512..1023 = z, 1024..1535 = n
// k 0..511 = Wp (S pass), 512..1023 = w_hh (X pass)
__device__ __align__(128) __half g_Bh[2][G3][1024];

// ---------------- helpers ----------------
__device__ __forceinline__ uint32_t f2tf(float f) {
    uint32_t u;
    asm("cvt.rna.tf32.f32 %0, %1;" : "=r"(u) : "f"(f));
    return u;
}
__device__ __forceinline__ float sigm(float v) { return 1.f / (1.f + __expf(-v)); }
__device__ __forceinline__ float tanh_fast(float v) { return 1.f - 2.f / (__expf(2.f * v) + 1.f); }

__device__ __forceinline__ void cpasync16(uint32_t d, const void* s) {
    asm volatile("cp.async.cg.shared.global [%0], [%1], 16;" :: "r"(d), "l"(s));
}
__device__ __forceinline__ void cp_commit() { asm volatile("cp.async.commit_group;"); }
__device__ __forceinline__ void cp_wait1() { asm volatile("cp.async.wait_group 1;" ::: "memory"); }
__device__ __forceinline__ void cp_wait0() { asm volatile("cp.async.wait_group 0;" ::: "memory"); }

__device__ __forceinline__ uint32_t smem_u32(const void* p) {
    uint32_t a;
    asm("{ .reg .u64 t; cvta.to.shared.u64 t, %1; cvt.u32.u64 %0, t; }" : "=r"(a) : "l"(p));
    return a;
}

// fp16 mma, fp32 accum
__device__ __forceinline__ void mma16(float* c, uint32_t a0, uint32_t a1,
                                      uint32_t a2, uint32_t a3,
                                      uint32_t b0, uint32_t b1) {
    asm volatile(
        "mma.sync.aligned.m16n8k16.row.col.f32.f16.f16.f32 "
        "{%0,%1,%2,%3},{%4,%5,%6,%7},{%8,%9},{%0,%1,%2,%3};"
        : "+f"(c[0]), "+f"(c[1]), "+f"(c[2]), "+f"(c[3])
        : "r"(a0), "r"(a1), "r"(a2), "r"(a3), "r"(b0), "r"(b1));
}

// ---------------- dtype detection / prep / CSR ----------------
__global__ void k_detect(const int* __restrict__ A) {
    __shared__ int nz;
    if (threadIdx.x == 0) nz = 0;
    __syncthreads();
    if (A[2 * threadIdx.x + 1] != 0) atomicOr(&nz, 1);
    __syncthreads();
    if (threadIdx.x == 0) g_is64 = (nz == 0) ? 1 : 0;
}

__global__ void k_prep(const void* __restrict__ Ab, const void* __restrict__ Ib) {
    int idx = blockIdx.x * blockDim.x + threadIdx.x;
    int is64 = g_is64;
    if (idx < 2 * NE) {
        long long v = is64 ? ((const long long*)Ab)[idx]
                           : (long long)((const int*)Ab)[idx];
        if (idx < NE) g_src[idx] = (int)v;
        else          g_dst[idx - NE] = (int)v;
    } else if (idx < 2 * NE + NN) {
        int i = idx - 2 * NE;
        long long v = is64 ? ((const long long*)Ib)[i]
                           : (long long)((const int*)Ib)[i];
        g_inp[i] = (int)v;
    } else if (idx < 2 * NE + NN + NN + 1) {
        g_rowptr[idx - 2 * NE - NN] = 0;
    }
}

// x0h = fp16(emb[inputs])  (fp32 h for layer0 read from emb via g_inp later)
__global__ void k_gx0(const float* __restrict__ emb) {
    int i = blockIdx.x * blockDim.x + threadIdx.x;  // over NN*64 chunks of 8 halves
    if (i < NN * 64) {
        int row = i >> 6, c = i & 63;
        const float4* src = (const float4*)(emb + (size_t)g_inp[row] * HH + c * 8);
        float4 v0 = src[0], v1 = src[1];
        __half2 h0 = __floats2half2_rn(v0.x, v0.y);
        __half2 h1 = __floats2half2_rn(v0.z, v0.w);
        __half2 h2 = __floats2half2_rn(v1.x, v1.y);
        __half2 h3 = __floats2half2_rn(v1.z, v1.w);
        uint4 u;
        u.x = *(uint32_t*)&h0; u.y = *(uint32_t*)&h1;
        u.z = *(uint32_t*)&h2; u.w = *(uint32_t*)&h3;
        *(uint4*)(g_x0h + (size_t)row * HH + c * 8) = u;
    }
}

__global__ void k_hist() {
    int e = blockIdx.x * blockDim.x + threadIdx.x;
    if (e < NE) atomicAdd(&g_rowptr[g_dst[e] + 1], 1);
}

// ---- multi-block scan of g_rowptr[1..NN] ----
__global__ void k_scan1() {  // grid 49, block 1024: per-block inclusive scan
    __shared__ int sh[1024];
    int t = threadIdx.x;
    int i = blockIdx.x * 1024 + t;
    int v = (i < NN) ? g_rowptr[i + 1] : 0;
    sh[t] = v;
    __syncthreads();
    for (int off = 1; off < 1024; off <<= 1) {
        int u = (t >= off) ? sh[t - off] : 0;
        __syncthreads();
        sh[t] += u;
        __syncthreads();
    }
    if (i < NN) g_rowptr[i + 1] = sh[t];
    if (t == 1023) g_bsum[blockIdx.x] = sh[1023];
}

__global__ void k_scan2() {  // serial scan of 49 block sums (tiny)
    if (threadIdx.x == 0) {
        int run = 0;
        for (int b = 0; b < 49; b++) {
            int v = g_bsum[b];
            g_bsum[b] = run;
            run += v;
        }
    }
}

__global__ void k_scan3() {  // add block offsets
    int i = blockIdx.x * 1024 + threadIdx.x;
    if (i < NN) {
        int v = g_rowptr[i + 1] + g_bsum[blockIdx.x];
        g_rowptr[i + 1] = v;
    }
}

__global__ void k_cur() {
    int i = blockIdx.x * blockDim.x + threadIdx.x;
    if (i < NN) g_cursor[i] = g_rowptr[i];
}

__global__ void k_fill() {
    int e = blockIdx.x * blockDim.x + threadIdx.x;
    if (e < NE) {
        int p = atomicAdd(&g_cursor[g_dst[e]], 1);
        g_csr[p] = g_src[e];
    }
}

// S[node] = sum over in-edges of xh[src]; 4 nodes/block, 64 thr/node, 16B loads
__global__ void __launch_bounds__(256) k_gsum(int xsel) {
    const __half* __restrict__ X = xsel ? g_x1h : g_x0h;
    int node = blockIdx.x * 4 + (threadIdx.x >> 6);
    if (node >= NN) return;
    int t = threadIdx.x & 63;
    int beg = g_rowptr[node], end = g_rowptr[node + 1];
    float a[8];
#pragma unroll
    for (int q = 0; q < 8; q++) a[q] = 0.f;
    int j = beg;
    for (; j + 1 < end; j += 2) {
        int s0 = g_csr[j], s1 = g_csr[j + 1];
        uint4 u0 = *(const uint4*)(X + (size_t)s0 * HH + t * 8);
        uint4 u1 = *(const uint4*)(X + (size_t)s1 * HH + t * 8);
#pragma unroll
        for (int q = 0; q < 4; q++) {
            float2 f0 = __half22float2(*((__half2*)&u0 + q));
            float2 f1 = __half22float2(*((__half2*)&u1 + q));
            a[2 * q] += f0.x + f1.x;
            a[2 * q + 1] += f0.y + f1.y;
        }
    }
    if (j < end) {
        int s0 = g_csr[j];
        uint4 u0 = *(const uint4*)(X + (size_t)s0 * HH + t * 8);
#pragma unroll
        for (int q = 0; q < 4; q++) {
            float2 f0 = __half22float2(*((__half2*)&u0 + q));
            a[2 * q] += f0.x;
            a[2 * q + 1] += f0.y;
        }
    }
    uint4 o;
    __half2 h0 = __floats2half2_rn(a[0], a[1]);
    __half2 h1 = __floats2half2_rn(a[2], a[3]);
    __half2 h2 = __floats2half2_rn(a[4], a[5]);
    __half2 h3 = __floats2half2_rn(a[6], a[7]);
    o.x = *(uint32_t*)&h0; o.y = *(uint32_t*)&h1;
    o.z = *(uint32_t*)&h2; o.w = *(uint32_t*)&h3;
    *(uint4*)(g_Sh + (size_t)node * HH + t * 8) = o;
}

// ---------------- g_Bh k<512 : Wp[l] = W_l @ w_ih^T (tf32 mma, transposed) --
__global__ void __launch_bounds__(256) k_wp(const float* __restrict__ W,
                                            const float* __restrict__ Wih,
                                            int layer) {
    __shared__ __align__(16) uint32_t As[64][36];
    __shared__ __align__(16) uint32_t Bs[32][36];
    const int tid = threadIdx.x;
    const int lane = tid & 31, wid = tid >> 5;
    const int wm = wid & 3, wn = wid >> 2;
    const int g8 = lane >> 2, t4 = lane & 3;
    const int i0 = blockIdx.y * 64;   // k index of Wp
    const int c0 = blockIdx.x * 32;   // gate col
    float acc[8];
#pragma unroll
    for (int b = 0; b < 8; b++) acc[b] = 0.f;

    for (int kt = 0; kt < 16; kt++) {
        const int kk0 = kt * 32;
        __syncthreads();
#pragma unroll
        for (int r2 = 0; r2 < 2; r2++) {
            int v = tid + 256 * r2;
            int row = v >> 3, c4 = v & 7;
            float4 a = *(const float4*)(W + (size_t)(i0 + row) * HH + kk0 + c4 * 4);
            uint4 u; u.x = f2tf(a.x); u.y = f2tf(a.y); u.z = f2tf(a.z); u.w = f2tf(a.w);
            *(uint4*)&As[row][c4 * 4] = u;
        }
        {
            int col = tid >> 3, k4 = tid & 7;
            float4 b = *(const float4*)(Wih + (size_t)(c0 + col) * HH + kk0 + k4 * 4);
            uint4 u; u.x = f2tf(b.x); u.y = f2tf(b.y); u.z = f2tf(b.z); u.w = f2tf(b.w);
            *(uint4*)&Bs[col][k4 * 4] = u;
        }
        __syncthreads();
#pragma unroll
        for (int ks = 0; ks < 4; ks++) {
            const int kb = ks * 8;
            uint32_t a0 = As[wm * 16 + g8][kb + t4];
            uint32_t a1 = As[wm * 16 + g8 + 8][kb + t4];
            uint32_t a2 = As[wm * 16 + g8][kb + t4 + 4];
            uint32_t a3 = As[wm * 16 + g8 + 8][kb + t4 + 4];
#pragma unroll
            for (int nt = 0; nt < 2; nt++) {
                int nc = wn * 16 + nt * 8 + g8;
                uint32_t b0 = Bs[nc][kb + t4];
                uint32_t b1 = Bs[nc][kb + t4 + 4];
                asm volatile(
                    "mma.sync.aligned.m16n8k8.row.col.f32.tf32.tf32.f32 "
                    "{%0,%1,%2,%3},{%4,%5,%6,%7},{%8,%9},{%0,%1,%2,%3};"
                    : "+f"(acc[nt * 4 + 0]), "+f"(acc[nt * 4 + 1]),
                      "+f"(acc[nt * 4 + 2]), "+f"(acc[nt * 4 + 3])
                    : "r"(a0), "r"(a1), "r"(a2), "r"(a3), "r"(b0), "r"(b1));
            }
        }
    }
#pragma unroll
    for (int nt = 0; nt < 2; nt++)
#pragma unroll
        for (int j = 0; j < 4; j++) {
            int krow = i0 + wm * 16 + g8 + ((j >> 1) << 3);
            int col = c0 + wn * 16 + nt * 8 + t4 * 2 + (j & 1);
            g_Bh[layer][col][krow] = __float2half_rn(acc[nt * 4 + j]);
        }
}

// ---------------- g_Bh k in [512:1024) : w_hh (row copy, fp16) -------------
__global__ void k_whh(const float* __restrict__ whh) {
    int i = blockIdx.x * blockDim.x + threadIdx.x;  // over 1536*128 float4
    if (i < G3 * (HH / 4)) {
        int row = i >> 7, c4 = i & 127;
        float4 v = ((const float4*)(whh + (size_t)row * HH))[c4];
        __half2 h0 = __floats2half2_rn(v.x, v.y);
        __half2 h1 = __floats2half2_rn(v.z, v.w);
        uint2 u = make_uint2(*(uint32_t*)&h0, *(uint32_t*)&h1);
        *(uint2*)&g_Bh[0][row][512 + c4 * 4] = u;
        *(uint2*)&g_Bh[1][row][512 + c4 * 4] = u;
    }
}

// ---------------- fused fp16 GEMM + GRU, merged K=1024, 3-stage pipeline ----
// Block tile: 128 m x 64 n-cols. 16 warps: wm=wid&3 (m32), wn=wid>>2 (n16).
// k-tile = 64 halves. 16 tiles (8 S-pass + 8 X-pass).
#define STRIDE_H 72                       // halves per smem row (64 + 8 pad)
#define ST_A (128 * STRIDE_H * 2)         // 18432 B
#define ST_B (192 * STRIDE_H * 2)         // 27648 B
#define ST_SZ (ST_A + ST_B)               // 46080 B
#define N_STAGE 3
#define SM_TOTAL (N_STAGE * ST_SZ)        // 138240 B

__global__ void __launch_bounds__(512, 1) k_fused(int layer, int xsel, int final_out,
                                                  int use_inp,
                                                  const float* __restrict__ hsrc,
                                                  float* __restrict__ dout,
                                                  const float* __restrict__ bih,
                                                  const float* __restrict__ bhh) {
    extern __shared__ __align__(16) char smem[];
    const uint32_t sbase = smem_u32(smem);

    const __half* __restrict__ Xh = xsel ? g_x1h : g_x0h;
    const __half* __restrict__ Bh = &g_Bh[layer][0][0];
    float* __restrict__ out = final_out ? dout : g_x1;
    // device-side resolution of the h-state base (g_x1 is a device symbol:
    // it must NOT be passed from host code as a kernel argument)
    const float* __restrict__ hbase = use_inp ? hsrc : g_x1;

    const int tid = threadIdx.x;
    const int lane = tid & 31, wid = tid >> 5;
    const int wm = wid & 3, wn = wid >> 2;
    const int g8 = lane >> 2, t4 = lane & 3;
    const int i0 = blockIdx.y * 128;
    const int c0 = blockIdx.x * 64;

    float accR[2][2][4], accZ[2][2][4], accN1[2][2][4], accN2[2][2][4];
#pragma unroll
    for (int mf = 0; mf < 2; mf++)
#pragma unroll
        for (int nf = 0; nf < 2; nf++)
#pragma unroll
            for (int j = 0; j < 4; j++) {
                accR[mf][nf][j] = 0.f; accZ[mf][nf][j] = 0.f;
                accN1[mf][nf][j] = 0.f; accN2[mf][nf][j] = 0.f;
            }

    // ---- async tile loader: tile t in 0..15, pass = t>>3, kt = t&7 ----
    auto load_tile = [&](int s, int t) {
        const int pass = t >> 3;
        const int k0 = (t & 7) * 64;   // halves within the 512-half row
        const __half* Ap = pass ? Xh : g_Sh;
        const uint32_t sA = sbase + s * ST_SZ;
        const uint32_t sB = sA + ST_A;
#pragma unroll
        for (int i = 0; i < 2; i++) {   // A: 128 rows x 8 chunks of 16B
            int v = tid + 512 * i;
            int row = v >> 3, c = v & 7;
            int gr = i0 + row;
            if (gr >= NN) gr = NN - 1;  // dup rows discarded in epilogue
            const __half* src = Ap + (size_t)gr * HH + k0 + c * 8;
            cpasync16(sA + (uint32_t)(row * (STRIDE_H * 2) + c * 16), src);
        }
#pragma unroll
        for (int i = 0; i < 3; i++) {   // B: 192 cols x 8 chunks of 16B
            int v = tid + 512 * i;
            int col = v >> 3, c = v & 7;
            int gate = col >> 6, j = col & 63;
            const __half* src = Bh + (size_t)(gate * 512 + c0 + j) * 1024 +
                                pass * 512 + k0 + c * 8;
            cpasync16(sB + (uint32_t)(col * (STRIDE_H * 2) + c * 16), src);
        }
    };

    load_tile(0, 0);
    cp_commit();
    load_tile(1, 1);
    cp_commit();

    for (int t = 0; t < 16; t++) {
        if (t < 15) cp_wait1();   // tile t landed; t+1 still in flight
        else        cp_wait0();
        __syncthreads();          // all warps done with tile t-1's stage
        if (t + 2 < 16) {         // prefetch into stage (t+2)%3 (= stage of t-1)
            load_tile((t + 2) % N_STAGE, t + 2);
            cp_commit();
        }
        const int pass = t >> 3;
        const char* stg = smem + (t % N_STAGE) * ST_SZ;
        const __half* As = (const __half*)stg;
        const __half* Bs = (const __half*)(stg + ST_A);
#pragma unroll
        for (int ks = 0; ks < 4; ks++) {
            const int kb = ks * 16;
            uint32_t a[2][4];
#pragma unroll
            for (int mf = 0; mf < 2; mf++) {
                const __half* pa = As + (wm * 32 + mf * 16 + g8) * STRIDE_H + kb + 2 * t4;
                a[mf][0] = *(const uint32_t*)(pa);
                a[mf][1] = *(const uint32_t*)(pa + 8 * STRIDE_H);
                a[mf][2] = *(const uint32_t*)(pa + 8);
                a[mf][3] = *(const uint32_t*)(pa + 8 * STRIDE_H + 8);
            }
#pragma unroll
            for (int g = 0; g < 3; g++) {
#pragma unroll
                for (int nf = 0; nf < 2; nf++) {
                    int nc = wn * 16 + nf * 8 + g8;
                    const __half* pb = Bs + (g * 64 + nc) * STRIDE_H + kb + 2 * t4;
                    uint32_t b0 = *(const uint32_t*)(pb);
                    uint32_t b1 = *(const uint32_t*)(pb + 8);
#pragma unroll
                    for (int mf = 0; mf < 2; mf++) {
                        float* dst = (g == 0) ? accR[mf][nf]
                                   : (g == 1) ? accZ[mf][nf]
                                   : (pass == 0) ? accN1[mf][nf] : accN2[mf][nf];
                        mma16(dst, a[mf][0], a[mf][1], a[mf][2], a[mf][3], b0, b1);
                    }
                }
            }
        }
    }

    // ---- GRU epilogue ----
#pragma unroll
    for (int mf = 0; mf < 2; mf++)
#pragma unroll
        for (int nf = 0; nf < 2; nf++) {
            const int colb = c0 + wn * 16 + nf * 8 + t4 * 2;
#pragma unroll
            for (int half_ = 0; half_ < 2; half_++) {   // j pair: rows g8 / g8+8
                int row = i0 + wm * 32 + mf * 16 + g8 + half_ * 8;
                if (row < NN) {
                    size_t hr = use_inp ? (size_t)g_inp[row] : (size_t)row;
                    float2 hv = *(const float2*)(hbase + hr * HH + colb);
                    float o[2];
#pragma unroll
                    for (int q = 0; q < 2; q++) {
                        int j = half_ * 2 + q;
                        int cl = colb + q;
                        float vr = accR[mf][nf][j] + __ldg(bih + cl) + __ldg(bhh + cl);
                        float vz = accZ[mf][nf][j] + __ldg(bih + cl + HH) + __ldg(bhh + cl + HH);
                        float r = sigm(vr);
                        float z = sigm(vz);
                        float n = tanh_fast(accN1[mf][nf][j] + __ldg(bih + cl + 2 * HH) +
                                            r * (accN2[mf][nf][j] + __ldg(bhh + cl + 2 * HH)));
                        float h = (q == 0) ? hv.x : hv.y;
                        o[q] = (1.f - z) * n + z * h;
                    }
                    *(float2*)(out + (size_t)row * HH + colb) = make_float2(o[0], o[1]);
                    if (!final_out) {
                        __half2 hh = __floats2half2_rn(o[0], o[1]);
                        *(uint32_t*)(g_x1h + (size_t)row * HH + colb) = *(uint32_t*)&hh;
                    }
                }
            }
        }
}

// ---------------- launch ----------------
extern "C" void kernel_launch(void* const* d_in, const int* in_sizes, int n_in,
                              void* d_out, int out_size) {
    const void* inputs = d_in[0];
    const void* A      = d_in[1];
    const float* emb    = (const float*)d_in[2];
    const float* weight = (const float*)d_in[3];
    const float* w_ih   = (const float*)d_in[4];
    const float* w_hh   = (const float*)d_in[5];
    const float* b_ih   = (const float*)d_in[6];
    const float* b_hh   = (const float*)d_in[7];
    float* out = (float*)d_out;

    cudaFuncSetAttribute(k_fused, cudaFuncAttributeMaxDynamicSharedMemorySize, SM_TOTAL);

    k_detect<<<1, 128>>>((const int*)A);
    int T = 2 * NE + NN + NN + 1;
    k_prep<<<(T + 255) / 256, 256>>>(A, inputs);
    k_gx0<<<(NN * 64 + 255) / 256, 256>>>(emb);
    k_hist<<<(NE + 255) / 256, 256>>>();
    k_scan1<<<49, 1024>>>();
    k_scan2<<<1, 32>>>();
    k_scan3<<<49, 1024>>>();
    k_cur<<<(NN + 255) / 256, 256>>>();
    k_fill<<<(NE + 255) / 256, 256>>>();
    k_whh<<<(G3 * (HH / 4) + 255) / 256, 256>>>(w_hh);
    for (int l = 0; l < 2; l++)
        k_wp<<<dim3(G3 / 32, HH / 64), 256>>>(weight + (size_t)l * HH * HH, w_ih, l);
    // layer 0: h-state comes from emb via g_inp; layer 1: from g_x1 (device-side)
    k_gsum<<<(NN + 3) / 4, 256>>>(0);
    k_fused<<<dim3(HH / 64, (NN + 127) / 128), 512, SM_TOTAL>>>(
        0, 0, 0, 1, emb, out, b_ih, b_hh);
    k_gsum<<<(NN + 3) / 4, 256>>>(1);
    k_fused<<<dim3(HH / 64, (NN + 127) / 128), 512, SM_TOTAL>>>(
        1, 1, 1, 0, (const float*)nullptr, out, b_ih, b_hh);
}

// round 11
// speedup vs baseline: 3.8346x; 1.0517x over previous
#include <cuda_runtime.h>
#include <cuda_fp16.h>
#include <cstdint>

#define NN 50000
#define NE 200000
#define HH 512
#define G3 1536

// ---------------- device scratch (static, no allocation) ----------------
__device__ int g_is64;
__device__ int g_src[NE];
__device__ int g_dst[NE];
__device__ int g_inp[NN];
__device__ int g_rowptr[NN + 1];
__device__ int g_cursor[NN];
__device__ int g_csr[NE];
__device__ int g_bsum[64];
__device__ __align__(128) __half g_x0h[(size_t)NN * HH]; // fp16 node states
__device__ __align__(128) __half g_x1h[(size_t)NN * HH];
__device__ __align__(128) __half g_Sh[(size_t)NN * HH];
// g_Bh[l][gatecol][k] col-major fp16: cols 0..511 = r, 512..1023 = z, 1024..1535 = n
// k 0..511 = Wp (S pass), 512..1023 = w_hh (X pass)
__device__ __align__(128) __half g_Bh[2][G3][1024];

// ---------------- helpers ----------------
__device__ __forceinline__ uint32_t f2tf(float f) {
    uint32_t u;
    asm("cvt.rna.tf32.f32 %0, %1;" : "=r"(u) : "f"(f));
    return u;
}
__device__ __forceinline__ float sigm(float v) { return 1.f / (1.f + __expf(-v)); }
__device__ __forceinline__ float tanh_fast(float v) { return 1.f - 2.f / (__expf(2.f * v) + 1.f); }

__device__ __forceinline__ void cpasync16(uint32_t d, const void* s) {
    asm volatile("cp.async.cg.shared.global [%0], [%1], 16;" :: "r"(d), "l"(s));
}
__device__ __forceinline__ void cp_commit() { asm volatile("cp.async.commit_group;"); }
__device__ __forceinline__ void cp_wait1() { asm volatile("cp.async.wait_group 1;" ::: "memory"); }
__device__ __forceinline__ void cp_wait0() { asm volatile("cp.async.wait_group 0;" ::: "memory"); }

__device__ __forceinline__ uint32_t smem_u32(const void* p) {
    uint32_t a;
    asm("{ .reg .u64 t; cvta.to.shared.u64 t, %1; cvt.u32.u64 %0, t; }" : "=r"(a) : "l"(p));
    return a;
}

// fp16 mma, fp32 accum
__device__ __forceinline__ void mma16(float* c, uint32_t a0, uint32_t a1,
                                      uint32_t a2, uint32_t a3,
                                      uint32_t b0, uint32_t b1) {
    asm volatile(
        "mma.sync.aligned.m16n8k16.row.col.f32.f16.f16.f32 "
        "{%0,%1,%2,%3},{%4,%5,%6,%7},{%8,%9},{%0,%1,%2,%3};"
        : "+f"(c[0]), "+f"(c[1]), "+f"(c[2]), "+f"(c[3])
        : "r"(a0), "r"(a1), "r"(a2), "r"(a3), "r"(b0), "r"(b1));
}

// ---------------- dtype detection / prep / CSR ----------------
__global__ void k_detect(const int* __restrict__ A) {
    __shared__ int nz;
    if (threadIdx.x == 0) nz = 0;
    __syncthreads();
    if (A[2 * threadIdx.x + 1] != 0) atomicOr(&nz, 1);
    __syncthreads();
    if (threadIdx.x == 0) g_is64 = (nz == 0) ? 1 : 0;
}

__global__ void k_prep(const void* __restrict__ Ab, const void* __restrict__ Ib) {
    int idx = blockIdx.x * blockDim.x + threadIdx.x;
    int is64 = g_is64;
    if (idx < 2 * NE) {
        long long v = is64 ? ((const long long*)Ab)[idx]
                           : (long long)((const int*)Ab)[idx];
        if (idx < NE) g_src[idx] = (int)v;
        else          g_dst[idx - NE] = (int)v;
    } else if (idx < 2 * NE + NN) {
        int i = idx - 2 * NE;
        long long v = is64 ? ((const long long*)Ib)[i]
                           : (long long)((const int*)Ib)[i];
        g_inp[i] = (int)v;
    } else if (idx < 2 * NE + NN + NN + 1) {
        g_rowptr[idx - 2 * NE - NN] = 0;
    }
}

// x0h = fp16(emb[inputs])
__global__ void k_gx0(const float* __restrict__ emb) {
    int i = blockIdx.x * blockDim.x + threadIdx.x;  // over NN*64 chunks of 8 halves
    if (i < NN * 64) {
        int row = i >> 6, c = i & 63;
        const float4* src = (const float4*)(emb + (size_t)g_inp[row] * HH + c * 8);
        float4 v0 = src[0], v1 = src[1];
        __half2 h0 = __floats2half2_rn(v0.x, v0.y);
        __half2 h1 = __floats2half2_rn(v0.z, v0.w);
        __half2 h2 = __floats2half2_rn(v1.x, v1.y);
        __half2 h3 = __floats2half2_rn(v1.z, v1.w);
        uint4 u;
        u.x = *(uint32_t*)&h0; u.y = *(uint32_t*)&h1;
        u.z = *(uint32_t*)&h2; u.w = *(uint32_t*)&h3;
        *(uint4*)(g_x0h + (size_t)row * HH + c * 8) = u;
    }
}

__global__ void k_hist() {
    int e = blockIdx.x * blockDim.x + threadIdx.x;
    if (e < NE) atomicAdd(&g_rowptr[g_dst[e] + 1], 1);
}

// ---- multi-block scan of g_rowptr[1..NN] ----
__global__ void k_scan1() {  // grid 49, block 1024: per-block inclusive scan
    __shared__ int sh[1024];
    int t = threadIdx.x;
    int i = blockIdx.x * 1024 + t;
    int v = (i < NN) ? g_rowptr[i + 1] : 0;
    sh[t] = v;
    __syncthreads();
    for (int off = 1; off < 1024; off <<= 1) {
        int u = (t >= off) ? sh[t - off] : 0;
        __syncthreads();
        sh[t] += u;
        __syncthreads();
    }
    if (i < NN) g_rowptr[i + 1] = sh[t];
    if (t == 1023) g_bsum[blockIdx.x] = sh[1023];
}

__global__ void k_scan2() {  // serial scan of 49 block sums (tiny)
    if (threadIdx.x == 0) {
        int run = 0;
        for (int b = 0; b < 49; b++) {
            int v = g_bsum[b];
            g_bsum[b] = run;
            run += v;
        }
    }
}

__global__ void k_scan3() {  // add block offsets; emit cursor in the same pass
    int i = blockIdx.x * 1024 + threadIdx.x;
    if (i < NN) {
        int v = g_rowptr[i + 1] + g_bsum[blockIdx.x];
        g_rowptr[i + 1] = v;
        if (i + 1 < NN) g_cursor[i + 1] = v;
        if (i == 0) g_cursor[0] = 0;
    }
}

__global__ void k_fill() {
    int e = blockIdx.x * blockDim.x + threadIdx.x;
    if (e < NE) {
        int p = atomicAdd(&g_cursor[g_dst[e]], 1);
        g_csr[p] = g_src[e];
    }
}

// S[node] = sum over in-edges of xh[src]; 4 nodes/block, 64 thr/node, 16B loads
__global__ void __launch_bounds__(256) k_gsum(int xsel) {
    const __half* __restrict__ X = xsel ? g_x1h : g_x0h;
    int node = blockIdx.x * 4 + (threadIdx.x >> 6);
    if (node >= NN) return;
    int t = threadIdx.x & 63;
    int beg = g_rowptr[node], end = g_rowptr[node + 1];
    float a[8];
#pragma unroll
    for (int q = 0; q < 8; q++) a[q] = 0.f;
    int j = beg;
    for (; j + 1 < end; j += 2) {
        int s0 = g_csr[j], s1 = g_csr[j + 1];
        uint4 u0 = *(const uint4*)(X + (size_t)s0 * HH + t * 8);
        uint4 u1 = *(const uint4*)(X + (size_t)s1 * HH + t * 8);
#pragma unroll
        for (int q = 0; q < 4; q++) {
            float2 f0 = __half22float2(*((__half2*)&u0 + q));
            float2 f1 = __half22float2(*((__half2*)&u1 + q));
            a[2 * q] += f0.x + f1.x;
            a[2 * q + 1] += f0.y + f1.y;
        }
    }
    if (j < end) {
        int s0 = g_csr[j];
        uint4 u0 = *(const uint4*)(X + (size_t)s0 * HH + t * 8);
#pragma unroll
        for (int q = 0; q < 4; q++) {
            float2 f0 = __half22float2(*((__half2*)&u0 + q));
            a[2 * q] += f0.x;
            a[2 * q + 1] += f0.y;
        }
    }
    uint4 o;
    __half2 h0 = __floats2half2_rn(a[0], a[1]);
    __half2 h1 = __floats2half2_rn(a[2], a[3]);
    __half2 h2 = __floats2half2_rn(a[4], a[5]);
    __half2 h3 = __floats2half2_rn(a[6], a[7]);
    o.x = *(uint32_t*)&h0; o.y = *(uint32_t*)&h1;
    o.z = *(uint32_t*)&h2; o.w = *(uint32_t*)&h3;
    *(uint4*)(g_Sh + (size_t)node * HH + t * 8) = o;
}

// ---------------- g_Bh k<512 : Wp[l] = W_l @ w_ih^T (tf32 mma, transposed) --
__global__ void __launch_bounds__(256) k_wp(const float* __restrict__ W,
                                            const float* __restrict__ Wih,
                                            int layer) {
    __shared__ __align__(16) uint32_t As[64][36];
    __shared__ __align__(16) uint32_t Bs[32][36];
    const int tid = threadIdx.x;
    const int lane = tid & 31, wid = tid >> 5;
    const int wm = wid & 3, wn = wid >> 2;
    const int g8 = lane >> 2, t4 = lane & 3;
    const int i0 = blockIdx.y * 64;   // k index of Wp
    const int c0 = blockIdx.x * 32;   // gate col
    float acc[8];
#pragma unroll
    for (int b = 0; b < 8; b++) acc[b] = 0.f;

    for (int kt = 0; kt < 16; kt++) {
        const int kk0 = kt * 32;
        __syncthreads();
#pragma unroll
        for (int r2 = 0; r2 < 2; r2++) {
            int v = tid + 256 * r2;
            int row = v >> 3, c4 = v & 7;
            float4 a = *(const float4*)(W + (size_t)(i0 + row) * HH + kk0 + c4 * 4);
            uint4 u; u.x = f2tf(a.x); u.y = f2tf(a.y); u.z = f2tf(a.z); u.w = f2tf(a.w);
            *(uint4*)&As[row][c4 * 4] = u;
        }
        {
            int col = tid >> 3, k4 = tid & 7;
            float4 b = *(const float4*)(Wih + (size_t)(c0 + col) * HH + kk0 + k4 * 4);
            uint4 u; u.x = f2tf(b.x); u.y = f2tf(b.y); u.z = f2tf(b.z); u.w = f2tf(b.w);
            *(uint4*)&Bs[col][k4 * 4] = u;
        }
        __syncthreads();
#pragma unroll
        for (int ks = 0; ks < 4; ks++) {
            const int kb = ks * 8;
            uint32_t a0 = As[wm * 16 + g8][kb + t4];
            uint32_t a1 = As[wm * 16 + g8 + 8][kb + t4];
            uint32_t a2 = As[wm * 16 + g8][kb + t4 + 4];
            uint32_t a3 = As[wm * 16 + g8 + 8][kb + t4 + 4];
#pragma unroll
            for (int nt = 0; nt < 2; nt++) {
                int nc = wn * 16 + nt * 8 + g8;
                uint32_t b0 = Bs[nc][kb + t4];
                uint32_t b1 = Bs[nc][kb + t4 + 4];
                asm volatile(
                    "mma.sync.aligned.m16n8k8.row.col.f32.tf32.tf32.f32 "
                    "{%0,%1,%2,%3},{%4,%5,%6,%7},{%8,%9},{%0,%1,%2,%3};"
                    : "+f"(acc[nt * 4 + 0]), "+f"(acc[nt * 4 + 1]),
                      "+f"(acc[nt * 4 + 2]), "+f"(acc[nt * 4 + 3])
                    : "r"(a0), "r"(a1), "r"(a2), "r"(a3), "r"(b0), "r"(b1));
            }
        }
    }
#pragma unroll
    for (int nt = 0; nt < 2; nt++)
#pragma unroll
        for (int j = 0; j < 4; j++) {
            int krow = i0 + wm * 16 + g8 + ((j >> 1) << 3);
            int col = c0 + wn * 16 + nt * 8 + t4 * 2 + (j & 1);
            g_Bh[layer][col][krow] = __float2half_rn(acc[nt * 4 + j]);
        }
}

// ---------------- g_Bh k in [512:1024) : w_hh (row copy, fp16) -------------
__global__ void k_whh(const float* __restrict__ whh) {
    int i = blockIdx.x * blockDim.x + threadIdx.x;  // over 1536*128 float4
    if (i < G3 * (HH / 4)) {
        int row = i >> 7, c4 = i & 127;
        float4 v = ((const float4*)(whh + (size_t)row * HH))[c4];
        __half2 h0 = __floats2half2_rn(v.x, v.y);
        __half2 h1 = __floats2half2_rn(v.z, v.w);
        uint2 u = make_uint2(*(uint32_t*)&h0, *(uint32_t*)&h1);
        *(uint2*)&g_Bh[0][row][512 + c4 * 4] = u;
        *(uint2*)&g_Bh[1][row][512 + c4 * 4] = u;
    }
}

// ---------------- fused fp16 GEMM + GRU, merged K=1024, 3-stage pipeline ----
// Block tile: 128 m x 64 n-cols. 16 warps: wm=wid&3 (m32), wn=wid>>2 (n16).
// k-tile = 64 halves. 16 tiles (8 S-pass + 8 X-pass).
#define STRIDE_H 72                       // halves per smem row (64 + 8 pad)
#define ST_A (128 * STRIDE_H * 2)         // 18432 B
#define ST_B (192 * STRIDE_H * 2)         // 27648 B
#define ST_SZ (ST_A + ST_B)               // 46080 B
#define N_STAGE 3
#define SM_TOTAL (N_STAGE * ST_SZ)        // 138240 B

__global__ void __launch_bounds__(512, 1) k_fused(int layer, int xsel, int final_out,
                                                  float* __restrict__ dout,
                                                  const float* __restrict__ bih,
                                                  const float* __restrict__ bhh) {
    extern __shared__ __align__(16) char smem[];
    const uint32_t sbase = smem_u32(smem);

    const __half* __restrict__ Xh = xsel ? g_x1h : g_x0h;   // also the h-state
    const __half* __restrict__ Bh = &g_Bh[layer][0][0];

    const int tid = threadIdx.x;
    const int lane = tid & 31, wid = tid >> 5;
    const int wm = wid & 3, wn = wid >> 2;
    const int g8 = lane >> 2, t4 = lane & 3;
    const int i0 = blockIdx.y * 128;
    const int c0 = blockIdx.x * 64;

    float accR[2][2][4], accZ[2][2][4], accN1[2][2][4], accN2[2][2][4];
#pragma unroll
    for (int mf = 0; mf < 2; mf++)
#pragma unroll
        for (int nf = 0; nf < 2; nf++)
#pragma unroll
            for (int j = 0; j < 4; j++) {
                accR[mf][nf][j] = 0.f; accZ[mf][nf][j] = 0.f;
                accN1[mf][nf][j] = 0.f; accN2[mf][nf][j] = 0.f;
            }

    // ---- async tile loader: tile t in 0..15, pass = t>>3, kt = t&7 ----
    auto load_tile = [&](int s, int t) {
        const int pass = t >> 3;
        const int k0 = (t & 7) * 64;   // halves within the 512-half row
        const __half* Ap = pass ? Xh : g_Sh;
        const uint32_t sA = sbase + s * ST_SZ;
        const uint32_t sB = sA + ST_A;
#pragma unroll
        for (int i = 0; i < 2; i++) {   // A: 128 rows x 8 chunks of 16B
            int v = tid + 512 * i;
            int row = v >> 3, c = v & 7;
            int gr = i0 + row;
            if (gr >= NN) gr = NN - 1;  // dup rows discarded in epilogue
            const __half* src = Ap + (size_t)gr * HH + k0 + c * 8;
            cpasync16(sA + (uint32_t)(row * (STRIDE_H * 2) + c * 16), src);
        }
#pragma unroll
        for (int i = 0; i < 3; i++) {   // B: 192 cols x 8 chunks of 16B
            int v = tid + 512 * i;
            int col = v >> 3, c = v & 7;
            int gate = col >> 6, j = col & 63;
            const __half* src = Bh + (size_t)(gate * 512 + c0 + j) * 1024 +
                                pass * 512 + k0 + c * 8;
            cpasync16(sB + (uint32_t)(col * (STRIDE_H * 2) + c * 16), src);
        }
    };

    load_tile(0, 0);
    cp_commit();
    load_tile(1, 1);
    cp_commit();

    for (int t = 0; t < 16; t++) {
        if (t < 15) cp_wait1();   // tile t landed; t+1 still in flight
        else        cp_wait0();
        __syncthreads();          // all warps done with tile t-1's stage
        if (t + 2 < 16) {         // prefetch into stage (t+2)%3 (= stage of t-1)
            load_tile((t + 2) % N_STAGE, t + 2);
            cp_commit();
        }
        const int pass = t >> 3;
        const char* stg = smem + (t % N_STAGE) * ST_SZ;
        const __half* As = (const __half*)stg;
        const __half* Bs = (const __half*)(stg + ST_A);
#pragma unroll
        for (int ks = 0; ks < 4; ks++) {
            const int kb = ks * 16;
            uint32_t a[2][4];
#pragma unroll
            for (int mf = 0; mf < 2; mf++) {
                const __half* pa = As + (wm * 32 + mf * 16 + g8) * STRIDE_H + kb + 2 * t4;
                a[mf][0] = *(const uint32_t*)(pa);
                a[mf][1] = *(const uint32_t*)(pa + 8 * STRIDE_H);
                a[mf][2] = *(const uint32_t*)(pa + 8);
                a[mf][3] = *(const uint32_t*)(pa + 8 * STRIDE_H + 8);
            }
#pragma unroll
            for (int g = 0; g < 3; g++) {
#pragma unroll
                for (int nf = 0; nf < 2; nf++) {
                    int nc = wn * 16 + nf * 8 + g8;
                    const __half* pb = Bs + (g * 64 + nc) * STRIDE_H + kb + 2 * t4;
                    uint32_t b0 = *(const uint32_t*)(pb);
                    uint32_t b1 = *(const uint32_t*)(pb + 8);
#pragma unroll
                    for (int mf = 0; mf < 2; mf++) {
                        float* dst = (g == 0) ? accR[mf][nf]
                                   : (g == 1) ? accZ[mf][nf]
                                   : (pass == 0) ? accN1[mf][nf] : accN2[mf][nf];
                        mma16(dst, a[mf][0], a[mf][1], a[mf][2], a[mf][3], b0, b1);
                    }
                }
            }
        }
    }

    // ---- GRU epilogue: h from fp16 Xh (sequential rows) ----
#pragma unroll
    for (int mf = 0; mf < 2; mf++)
#pragma unroll
        for (int nf = 0; nf < 2; nf++) {
            const int colb = c0 + wn * 16 + nf * 8 + t4 * 2;
#pragma unroll
            for (int half_ = 0; half_ < 2; half_++) {   // j pair: rows g8 / g8+8
                int row = i0 + wm * 32 + mf * 16 + g8 + half_ * 8;
                if (row < NN) {
                    uint32_t hu = *(const uint32_t*)(Xh + (size_t)row * HH + colb);
                    float2 hv = __half22float2(*(__half2*)&hu);
                    float o[2];
#pragma unroll
                    for (int q = 0; q < 2; q++) {
                        int j = half_ * 2 + q;
                        int cl = colb + q;
                        float vr = accR[mf][nf][j] + __ldg(bih + cl) + __ldg(bhh + cl);
                        float vz = accZ[mf][nf][j] + __ldg(bih + cl + HH) + __ldg(bhh + cl + HH);
                        float r = sigm(vr);
                        float z = sigm(vz);
                        float n = tanh_fast(accN1[mf][nf][j] + __ldg(bih + cl + 2 * HH) +
                                            r * (accN2[mf][nf][j] + __ldg(bhh + cl + 2 * HH)));
                        float h = (q == 0) ? hv.x : hv.y;
                        o[q] = (1.f - z) * n + z * h;
                    }
                    if (final_out) {
                        *(float2*)(dout + (size_t)row * HH + colb) = make_float2(o[0], o[1]);
                    } else {
                        __half2 hh = __floats2half2_rn(o[0], o[1]);
                        *(uint32_t*)(g_x1h + (size_t)row * HH + colb) = *(uint32_t*)&hh;
                    }
                }
            }
        }
}

// ---------------- launch ----------------
extern "C" void kernel_launch(void* const* d_in, const int* in_sizes, int n_in,
                              void* d_out, int out_size) {
    const void* inputs = d_in[0];
    const void* A      = d_in[1];
    const float* emb    = (const float*)d_in[2];
    const float* weight = (const float*)d_in[3];
    const float* w_ih   = (const float*)d_in[4];
    const float* w_hh   = (const float*)d_in[5];
    const float* b_ih   = (const float*)d_in[6];
    const float* b_hh   = (const float*)d_in[7];
    float* out = (float*)d_out;

    cudaFuncSetAttribute(k_fused, cudaFuncAttributeMaxDynamicSharedMemorySize, SM_TOTAL);

    k_detect<<<1, 128>>>((const int*)A);
    int T = 2 * NE + NN + NN + 1;
    k_prep<<<(T + 255) / 256, 256>>>(A, inputs);
    k_gx0<<<(NN * 64 + 255) / 256, 256>>>(emb);
    k_hist<<<(NE + 255) / 256, 256>>>();
    k_scan1<<<49, 1024>>>();
    k_scan2<<<1, 32>>>();
    k_scan3<<<49, 1024>>>();
    k_fill<<<(NE + 255) / 256, 256>>>();
    k_whh<<<(G3 * (HH / 4) + 255) / 256, 256>>>(w_hh);
    for (int l = 0; l < 2; l++)
        k_wp<<<dim3(G3 / 32, HH / 64), 256>>>(weight + (size_t)l * HH * HH, w_ih, l);
    k_gsum<<<(NN + 3) / 4, 256>>>(0);
    k_fused<<<dim3(HH / 64, (NN + 127) / 128), 512, SM_TOTAL>>>(
        0, 0, 0, out, b_ih, b_hh);
    k_gsum<<<(NN + 3) / 4, 256>>>(1);
    k_fused<<<dim3(HH / 64, (NN + 127) / 128), 512, SM_TOTAL>>>(
        1, 1, 1, out, b_ih, b_hh);
}